// round 10
// baseline (speedup 1.0000x reference)
#include <cuda_runtime.h>
#include <cuda_bf16.h>
#include <math.h>
#include <stdint.h>

#define DIM  256
#define NH   4
#define HC   64
#define NTOK 49
#define NB   4096

// Standardized weights in ks-paired mma-FRAGMENT order (uint4 granularity):
// uint4 index = (nblk*8 + kp)*32 + lane
__device__ __align__(16) __nv_bfloat16 g_Wbf[5][DIM * DIM];
__device__ float g_b[5][DIM];
// fp32 residual stream scratch, one row-block per sample (L2-resident working set)
__device__ float g_R[NB][NTOK * DIM];

#define W_MAT_U4 8192   // uint4 per 256x256 bf16 matrix

// ---------------------------------------------------------------------------
// Prologue: weight standardization -> ks-paired fragment-ordered bf16
// ---------------------------------------------------------------------------
__global__ __launch_bounds__(256) void std_kernel(
    const float* __restrict__ qw, const float* __restrict__ qb,
    const float* __restrict__ kw, const float* __restrict__ kb,
    const float* __restrict__ vw, const float* __restrict__ vb,
    const float* __restrict__ fiw, const float* __restrict__ fib,
    const float* __restrict__ fow, const float* __restrict__ fob)
{
    const float* wptr[5] = {qw, kw, vw, fiw, fow};
    const float* bptr[5] = {qb, kb, vb, fib, fob};
    __shared__ float s_sum[8], s_sq[8];
    int bx = blockIdx.x, t = threadIdx.x;

    float val;
    if (bx < 5 * DIM) val = wptr[bx >> 8][(bx & 255) * DIM + t];
    else              val = bptr[bx - 5 * DIM][t];

    float s = val, q = val * val;
    #pragma unroll
    for (int o = 16; o > 0; o >>= 1) {
        s += __shfl_xor_sync(0xFFFFFFFFu, s, o);
        q += __shfl_xor_sync(0xFFFFFFFFu, q, o);
    }
    if ((t & 31) == 0) { s_sum[t >> 5] = s; s_sq[t >> 5] = q; }
    __syncthreads();
    int h = t >> 6;
    float sum = s_sum[2*h] + s_sum[2*h+1];
    float sq  = s_sq [2*h] + s_sq [2*h+1];
    float mean = sum * (1.0f/64.0f);
    float var  = fmaxf(sq * (1.0f/64.0f) - mean*mean, 0.0f);
    float r    = (val - mean) / (sqrtf(var) * 16.0f);

    if (bx < 5 * DIM) {
        int m = bx >> 8, k = bx & 255, c = t;
        int kp   = k >> 5;
        int kodd = (k >> 4) & 1;
        int half = (k >> 3) & 1;
        int pos2 = (k >> 1) & 3;
        int par  = k & 1;
        int lane = (c & 7) * 4 + pos2;
        int nblk = c >> 3;
        size_t idx = ((size_t)(((nblk * 8 + kp) * 32 + lane)) << 3)
                   + (size_t)(kodd * 4 + half * 2 + par);
        ((__nv_bfloat16*)g_Wbf)[(size_t)m * DIM * DIM + idx] = __float2bfloat16(r);
    } else {
        g_b[bx - 5 * DIM][t] = r;
    }
}

// ---------------------------------------------------------------------------
// PTX helpers
// ---------------------------------------------------------------------------
__device__ __forceinline__ uint32_t s2u(const void* p) {
    uint32_t a;
    asm("{ .reg .u64 t; cvta.to.shared.u64 t, %1; cvt.u32.u64 %0, t; }" : "=r"(a) : "l"(p));
    return a;
}
__device__ __forceinline__ void ldsm4(uint32_t* r, uint32_t a) {
    asm volatile("ldmatrix.sync.aligned.m8n8.x4.shared.b16 {%0,%1,%2,%3}, [%4];"
                 : "=r"(r[0]), "=r"(r[1]), "=r"(r[2]), "=r"(r[3]) : "r"(a));
}
__device__ __forceinline__ void ldsm2(uint32_t* r, uint32_t a) {
    asm volatile("ldmatrix.sync.aligned.m8n8.x2.shared.b16 {%0,%1}, [%2];"
                 : "=r"(r[0]), "=r"(r[1]) : "r"(a));
}
__device__ __forceinline__ void mma16816(float* d, const uint32_t* a, const uint32_t* b) {
    asm volatile("mma.sync.aligned.m16n8k16.row.col.f32.bf16.bf16.f32 "
                 "{%0,%1,%2,%3}, {%4,%5,%6,%7}, {%8,%9}, {%0,%1,%2,%3};"
                 : "+f"(d[0]), "+f"(d[1]), "+f"(d[2]), "+f"(d[3])
                 : "r"(a[0]), "r"(a[1]), "r"(a[2]), "r"(a[3]), "r"(b[0]), "r"(b[1]));
}
__device__ __forceinline__ uint32_t bfx2(float lo, float hi) {   // low half = lo
    uint32_t r;
    asm("cvt.rn.bf16x2.f32 %0, %1, %2;" : "=r"(r) : "f"(hi), "f"(lo));
    return r;
}

// ---------------------------------------------------------------------------
// smem regions (bytes), aliased by lifetime:
//  SM_X  : x tile (64x264 bf16, stride 528) -> x2 tile -> t3 tile
//  SM_QP : Q tile (stride 528)              -> P tiles 4 x (64 x 72 bf16, stride 144)
//  SM_KV : K tile (stride 528)              -> VT (256 ch x 72 bf16, stride 144)
// ---------------------------------------------------------------------------
#define SM_X    0        // 33792
#define SM_QP   33792    // 36864
#define SM_KV   70656    // 36864
#define SM_BIAS 107520   // 5120
#define SMEM_TOTAL 112640

// One 64x256x256 GEMM, 8 warps: warp w computes m64 x n32 (cols w*32..).
// A from smem (stride 528); B via LDG.128 from ks-paired fragment order.
__device__ __forceinline__ void mma_gemm(uint32_t aBase, const uint4* __restrict__ Wf,
                                         float acc[4][4][4], uint32_t aoff)
{
    #pragma unroll
    for (int mf = 0; mf < 4; mf++)
        #pragma unroll
        for (int nf = 0; nf < 4; nf++)
            #pragma unroll
            for (int q = 0; q < 4; q++) acc[mf][nf][q] = 0.0f;

    uint4 breg[2][4];
    #pragma unroll
    for (int nf = 0; nf < 4; nf++) breg[0][nf] = __ldg(Wf + nf * 256);

    #pragma unroll
    for (int kp = 0; kp < 8; kp++) {
        const int cur = kp & 1, nxt = cur ^ 1;
        if (kp < 7) {
            #pragma unroll
            for (int nf = 0; nf < 4; nf++)
                breg[nxt][nf] = __ldg(Wf + nf * 256 + (kp + 1) * 32);
        }
        uint32_t a[4][4];
        #pragma unroll
        for (int mf = 0; mf < 4; mf++)
            ldsm4(a[mf], aBase + aoff + (uint32_t)(mf * 16 * 528 + (2*kp) * 32));
        #pragma unroll
        for (int nf = 0; nf < 4; nf++) {
            uint32_t b0[2] = { breg[cur][nf].x, breg[cur][nf].y };
            #pragma unroll
            for (int mf = 0; mf < 4; mf++) mma16816(acc[mf][nf], a[mf], b0);
        }
        #pragma unroll
        for (int mf = 0; mf < 4; mf++)
            ldsm4(a[mf], aBase + aoff + (uint32_t)(mf * 16 * 528 + (2*kp+1) * 32));
        #pragma unroll
        for (int nf = 0; nf < 4; nf++) {
            uint32_t b1[2] = { breg[cur][nf].z, breg[cur][nf].w };
            #pragma unroll
            for (int mf = 0; mf < 4; mf++) mma16816(acc[mf][nf], a[mf], b1);
        }
    }
}

__global__ __launch_bounds__(256, 2) void irmb_kernel(
    const float* __restrict__ x, float* __restrict__ out)
{
    extern __shared__ char sm[];
    const uint32_t sb = s2u(sm);
    const int tid = threadIdx.x, w = tid >> 5, lane = tid & 31;

    float* sBias = (float*)(sm + SM_BIAS);
    const float* xb = x + (size_t)blockIdx.x * (NTOK * DIM);
    float* ob = out + (size_t)blockIdx.x * (NTOK * DIM);
    float* Rb = g_R[blockIdx.x];

    // zero x tile (incl. pad rows/cols), load biases
    {
        uint32_t* z = (uint32_t*)(sm + SM_X);
        for (int i = tid; i < 8448; i += 256) z[i] = 0;
        const float* gb = (const float*)g_b;
        for (int i = tid; i < 1280; i += 256) sBias[i] = gb[i];
    }
    __syncthreads();
    for (int i = tid; i < NTOK * DIM; i += 256) {
        int r = i >> 8, c = i & 255;
        *(__nv_bfloat16*)(sm + SM_X + r * 528 + c * 2) = __float2bfloat16(xb[i]);
    }
    __syncthreads();

    // lane-mapping constants
    const int gq = lane >> 3, iq = lane & 7;
    const uint32_t aoff = (uint32_t)((iq + (gq & 1) * 8) * 528 + ((gq >> 1) * 8) * 2);
    const int r0 = lane >> 2, c0 = 2 * (lane & 3);
    const uint4* W4 = (const uint4*)g_Wbf;
    const int wfoff = w * 1024 + lane;     // uint4 units (nblk base = w*4)

    float acc[4][4][4];

    // ---- Q -> SM_QP (bf16 tile, stride 528; all 64 rows) ----
    mma_gemm(sb + SM_X, W4 + wfoff, acc, aoff);
    #pragma unroll
    for (int mf = 0; mf < 4; mf++)
        #pragma unroll
        for (int nf = 0; nf < 4; nf++)
            #pragma unroll
            for (int rr = 0; rr < 2; rr++) {
                int r = mf * 16 + r0 + rr * 8;
                int c = w * 32 + nf * 8 + c0;
                *(uint32_t*)(sm + SM_QP + r * 528 + c * 2) =
                    bfx2(acc[mf][nf][rr*2] + sBias[c], acc[mf][nf][rr*2+1] + sBias[c+1]);
            }

    // ---- K -> SM_KV ----
    mma_gemm(sb + SM_X, W4 + W_MAT_U4 + wfoff, acc, aoff);
    #pragma unroll
    for (int mf = 0; mf < 4; mf++)
        #pragma unroll
        for (int nf = 0; nf < 4; nf++)
            #pragma unroll
            for (int rr = 0; rr < 2; rr++) {
                int r = mf * 16 + r0 + rr * 8;
                int c = w * 32 + nf * 8 + c0;
                *(uint32_t*)(sm + SM_KV + r * 528 + c * 2) =
                    bfx2(acc[mf][nf][rr*2] + sBias[256+c], acc[mf][nf][rr*2+1] + sBias[256+c+1]);
            }
    __syncthreads();

    // ---- QK^T for warp's 2 heads into registers (reads Q + K tiles) ----
    const int mfs = w & 3, hw = w >> 2;
    float sc2[2][7][4];
    #pragma unroll
    for (int p = 0; p < 2; p++) {
        int h = 2 * p + hw;
        #pragma unroll
        for (int nf = 0; nf < 7; nf++)
            #pragma unroll
            for (int q = 0; q < 4; q++) sc2[p][nf][q] = 0.0f;
        uint32_t qbase = sb + SM_QP + (uint32_t)(mfs * 16 * 528) + aoff + (uint32_t)(h * 128);
        uint32_t kb    = sb + SM_KV + (uint32_t)((lane & 7) * 528) + (uint32_t)(h * 128)
                       + (uint32_t)(((lane >> 3) & 1) * 16);
        #pragma unroll
        for (int ks = 0; ks < 4; ks++) {
            uint32_t a[4];
            ldsm4(a, qbase + ks * 32);
            #pragma unroll
            for (int nf = 0; nf < 7; nf++) {
                uint32_t b[2];
                ldsm2(b, kb + (uint32_t)(nf * 8 * 528) + ks * 32);
                mma16816(sc2[p][nf], a, b);
            }
        }
    }
    __syncthreads();   // all Q/K reads done; regions may be overwritten

    // ---- zero VT region (K dead); softmax + P store into SM_QP ----
    {
        uint32_t* kvz = (uint32_t*)(sm + SM_KV);
        for (int i = tid; i < 9216; i += 256) kvz[i] = 0;
    }
    #pragma unroll
    for (int p = 0; p < 2; p++) {
        int h = 2 * p + hw;
        #pragma unroll
        for (int half = 0; half < 2; half++) {
            int r = mfs * 16 + r0 + half * 8;
            float vv[14];
            float m = -1e30f;
            #pragma unroll
            for (int nf = 0; nf < 7; nf++)
                #pragma unroll
                for (int j = 0; j < 2; j++) {
                    int kk = nf * 8 + c0 + j;
                    float s = (kk < NTOK) ? sc2[p][nf][half*2 + j] * 0.125f : -1e30f;
                    vv[nf*2 + j] = s;
                    m = fmaxf(m, s);
                }
            m = fmaxf(m, __shfl_xor_sync(0xFFFFFFFFu, m, 1));
            m = fmaxf(m, __shfl_xor_sync(0xFFFFFFFFu, m, 2));
            float sum = 0.0f;
            #pragma unroll
            for (int t = 0; t < 14; t++) {
                float e = (vv[t] > -1e29f) ? __expf(vv[t] - m) : 0.0f;
                vv[t] = e; sum += e;
            }
            sum += __shfl_xor_sync(0xFFFFFFFFu, sum, 1);
            sum += __shfl_xor_sync(0xFFFFFFFFu, sum, 2);
            float inv = 1.0f / sum;
            #pragma unroll
            for (int nf = 0; nf < 7; nf++) {
                uint32_t pk = (r < NTOK) ? bfx2(vv[nf*2] * inv, vv[nf*2+1] * inv) : 0u;
                *(uint32_t*)(sm + SM_QP + h * 9216 + r * 144 + (nf * 8 + c0) * 2) = pk;
            }
            // nf = 7 column block: explicit zeros (kk 56..63)
            *(uint32_t*)(sm + SM_QP + h * 9216 + r * 144 + (56 + c0) * 2) = 0u;
        }
    }
    __syncthreads();   // VT zero + P visible

    // ---- V: V' = (xWv+b)*0.1 + x*0.95 -> g_R fp32 + VT bf16 (SM_KV) ----
    mma_gemm(sb + SM_X, W4 + 2 * W_MAT_U4 + wfoff, acc, aoff);
    #pragma unroll
    for (int mf = 0; mf < 4; mf++)
        #pragma unroll
        for (int nf = 0; nf < 4; nf++)
            #pragma unroll
            for (int rr = 0; rr < 2; rr++) {
                int r = mf * 16 + r0 + rr * 8;
                if (r < NTOK) {
                    int c = w * 32 + nf * 8 + c0;
                    float v0 = (acc[mf][nf][rr*2]   + sBias[512+c])   * 0.1f + xb[r*DIM+c]   * 0.95f;
                    float v1 = (acc[mf][nf][rr*2+1] + sBias[512+c+1]) * 0.1f + xb[r*DIM+c+1] * 0.95f;
                    Rb[r*DIM+c] = v0; Rb[r*DIM+c+1] = v1;
                    *(__nv_bfloat16*)(sm + SM_KV + c * 144 + r * 2)       = __float2bfloat16(v0);
                    *(__nv_bfloat16*)(sm + SM_KV + (c + 1) * 144 + r * 2) = __float2bfloat16(v1);
                }
            }
    __syncthreads();

    // ---- PV: x2 = (P @ V')*0.1 + V'*0.95 -> g_R + bf16 tile in SM_X ----
    {
        const int nfr = (w >> 2) * 4;
        const uint32_t poff = (uint32_t)((iq + (gq & 1) * 8) * 144 + ((gq >> 1) * 8) * 2);
        #pragma unroll
        for (int h = 0; h < 4; h++) {
            float pa[4][4];
            #pragma unroll
            for (int nf = 0; nf < 4; nf++)
                #pragma unroll
                for (int q = 0; q < 4; q++) pa[nf][q] = 0.0f;

            uint32_t pbase = sb + SM_QP + (uint32_t)(h * 9216 + mfs * 16 * 144) + poff;
            uint32_t vb = sb + SM_KV + (uint32_t)((h * 64 + nfr * 8 + (lane & 7)) * 144)
                        + (uint32_t)(((lane >> 3) & 1) * 16);
            #pragma unroll
            for (int ks = 0; ks < 4; ks++) {
                uint32_t a[4];
                ldsm4(a, pbase + ks * 32);
                #pragma unroll
                for (int nf = 0; nf < 4; nf++) {
                    uint32_t b[2];
                    ldsm2(b, vb + (uint32_t)(nf * 8 * 144) + ks * 32);
                    mma16816(pa[nf], a, b);
                }
            }
            #pragma unroll
            for (int nf = 0; nf < 4; nf++)
                #pragma unroll
                for (int rr = 0; rr < 2; rr++) {
                    int r = mfs * 16 + r0 + rr * 8;
                    int c = h * 64 + nfr * 8 + nf * 8 + c0;
                    if (r < NTOK) {
                        float a0 = pa[nf][rr*2]   * 0.1f + Rb[r*DIM+c]   * 0.95f;
                        float a1 = pa[nf][rr*2+1] * 0.1f + Rb[r*DIM+c+1] * 0.95f;
                        Rb[r*DIM+c] = a0; Rb[r*DIM+c+1] = a1;
                        *(uint32_t*)(sm + SM_X + r * 528 + c * 2) = bfx2(a0, a1);
                    } else {
                        *(uint32_t*)(sm + SM_X + r * 528 + c * 2) = 0u;
                    }
                }
        }
    }
    __syncthreads();

    // ---- FFN in ----
    mma_gemm(sb + SM_X, W4 + 3 * W_MAT_U4 + wfoff, acc, aoff);
    __syncthreads();           // all x2 reads done before in-place overwrite
    #pragma unroll
    for (int mf = 0; mf < 4; mf++)
        #pragma unroll
        for (int nf = 0; nf < 4; nf++)
            #pragma unroll
            for (int rr = 0; rr < 2; rr++) {
                int r = mf * 16 + r0 + rr * 8;
                int c = w * 32 + nf * 8 + c0;
                if (r < NTOK) {
                    float t2a = (acc[mf][nf][rr*2]   + sBias[768+c])   * 0.1f + Rb[r*DIM+c]   * 0.95f;
                    float t2b = (acc[mf][nf][rr*2+1] + sBias[768+c+1]) * 0.1f + Rb[r*DIM+c+1] * 0.95f;
                    float t3a = (1.0f/(1.0f + __expf(-t2a)) - 0.5f) * 0.1f + t2a * 0.95f;
                    float t3b = (1.0f/(1.0f + __expf(-t2b)) - 0.5f) * 0.1f + t2b * 0.95f;
                    Rb[r*DIM+c] = t3a; Rb[r*DIM+c+1] = t3b;
                    *(uint32_t*)(sm + SM_X + r * 528 + c * 2) = bfx2(t3a, t3b);
                } else {
                    *(uint32_t*)(sm + SM_X + r * 528 + c * 2) = 0u;
                }
            }
    __syncthreads();

    // ---- FFN out ----
    mma_gemm(sb + SM_X, W4 + 4 * W_MAT_U4 + wfoff, acc, aoff);
    #pragma unroll
    for (int mf = 0; mf < 4; mf++)
        #pragma unroll
        for (int nf = 0; nf < 4; nf++)
            #pragma unroll
            for (int rr = 0; rr < 2; rr++) {
                int r = mf * 16 + r0 + rr * 8;
                if (r < NTOK) {
                    int c = w * 32 + nf * 8 + c0;
                    ob[r*DIM + c]   = (acc[mf][nf][rr*2]   + sBias[1024+c])   * 0.1f + Rb[r*DIM+c]   * 0.95f;
                    ob[r*DIM + c+1] = (acc[mf][nf][rr*2+1] + sBias[1024+c+1]) * 0.1f + Rb[r*DIM+c+1] * 0.95f;
                }
            }
}

// ---------------------------------------------------------------------------
extern "C" void kernel_launch(void* const* d_in, const int* in_sizes, int n_in,
                              void* d_out, int out_size)
{
    std_kernel<<<5 * DIM + 5, 256>>>(
        (const float*)d_in[1], (const float*)d_in[2],
        (const float*)d_in[3], (const float*)d_in[4],
        (const float*)d_in[5], (const float*)d_in[6],
        (const float*)d_in[7], (const float*)d_in[8],
        (const float*)d_in[9], (const float*)d_in[10]);

    cudaFuncSetAttribute(irmb_kernel,
                         cudaFuncAttributeMaxDynamicSharedMemorySize, SMEM_TOTAL);
    irmb_kernel<<<NB, 256, SMEM_TOTAL>>>((const float*)d_in[0], (float*)d_out);
}

// round 12
// speedup vs baseline: 1.2311x; 1.2311x over previous
#include <cuda_runtime.h>
#include <cuda_bf16.h>
#include <math.h>
#include <stdint.h>

#define DIM  256
#define NH   4
#define HC   64
#define NTOK 49
#define NB   4096
#define SMP  12544   // NTOK*DIM

// Standardized weights in ks-paired mma-FRAGMENT order (uint4 granularity):
// uint4 index = (nblk*8 + kp)*32 + lane (per matrix), matrices contiguous.
__device__ __align__(16) __nv_bfloat16 g_Wbf[5][DIM * DIM];
__device__ float g_b[5][DIM];
// fp32 residual stream scratch per sample
__device__ float g_R[NB][SMP];

#define W_MAT_U4 8192   // uint4 per 256x256 bf16 matrix

// ---------------------------------------------------------------------------
// Prologue: weight standardization -> ks-paired fragment-ordered bf16
// ---------------------------------------------------------------------------
__global__ __launch_bounds__(256) void std_kernel(
    const float* __restrict__ qw, const float* __restrict__ qb,
    const float* __restrict__ kw, const float* __restrict__ kb,
    const float* __restrict__ vw, const float* __restrict__ vb,
    const float* __restrict__ fiw, const float* __restrict__ fib,
    const float* __restrict__ fow, const float* __restrict__ fob)
{
    const float* wptr[5] = {qw, kw, vw, fiw, fow};
    const float* bptr[5] = {qb, kb, vb, fib, fob};
    __shared__ float s_sum[8], s_sq[8];
    int bx = blockIdx.x, t = threadIdx.x;

    float val;
    if (bx < 5 * DIM) val = wptr[bx >> 8][(bx & 255) * DIM + t];
    else              val = bptr[bx - 5 * DIM][t];

    float s = val, q = val * val;
    #pragma unroll
    for (int o = 16; o > 0; o >>= 1) {
        s += __shfl_xor_sync(0xFFFFFFFFu, s, o);
        q += __shfl_xor_sync(0xFFFFFFFFu, q, o);
    }
    if ((t & 31) == 0) { s_sum[t >> 5] = s; s_sq[t >> 5] = q; }
    __syncthreads();
    int h = t >> 6;
    float sum = s_sum[2*h] + s_sum[2*h+1];
    float sq  = s_sq [2*h] + s_sq [2*h+1];
    float mean = sum * (1.0f/64.0f);
    float var  = fmaxf(sq * (1.0f/64.0f) - mean*mean, 0.0f);
    float r    = (val - mean) / (sqrtf(var) * 16.0f);

    if (bx < 5 * DIM) {
        int m = bx >> 8, k = bx & 255, c = t;
        int kp   = k >> 5;
        int kodd = (k >> 4) & 1;
        int half = (k >> 3) & 1;
        int pos2 = (k >> 1) & 3;
        int par  = k & 1;
        int lane = (c & 7) * 4 + pos2;
        int nblk = c >> 3;
        size_t idx = ((size_t)(((nblk * 8 + kp) * 32 + lane)) << 3)
                   + (size_t)(kodd * 4 + half * 2 + par);
        ((__nv_bfloat16*)g_Wbf)[(size_t)m * DIM * DIM + idx] = __float2bfloat16(r);
    } else {
        g_b[bx - 5 * DIM][t] = r;
    }
}

// ---------------------------------------------------------------------------
// PTX helpers
// ---------------------------------------------------------------------------
__device__ __forceinline__ uint32_t s2u(const void* p) {
    uint32_t a;
    asm("{ .reg .u64 t; cvta.to.shared.u64 t, %1; cvt.u32.u64 %0, t; }" : "=r"(a) : "l"(p));
    return a;
}
__device__ __forceinline__ void ldsm4(uint32_t* r, uint32_t a) {
    asm volatile("ldmatrix.sync.aligned.m8n8.x4.shared.b16 {%0,%1,%2,%3}, [%4];"
                 : "=r"(r[0]), "=r"(r[1]), "=r"(r[2]), "=r"(r[3]) : "r"(a));
}
__device__ __forceinline__ void ldsm2(uint32_t* r, uint32_t a) {
    asm volatile("ldmatrix.sync.aligned.m8n8.x2.shared.b16 {%0,%1}, [%2];"
                 : "=r"(r[0]), "=r"(r[1]) : "r"(a));
}
__device__ __forceinline__ void mma16816(float* d, const uint32_t* a, const uint32_t* b) {
    asm volatile("mma.sync.aligned.m16n8k16.row.col.f32.bf16.bf16.f32 "
                 "{%0,%1,%2,%3}, {%4,%5,%6,%7}, {%8,%9}, {%0,%1,%2,%3};"
                 : "+f"(d[0]), "+f"(d[1]), "+f"(d[2]), "+f"(d[3])
                 : "r"(a[0]), "r"(a[1]), "r"(a[2]), "r"(a[3]), "r"(b[0]), "r"(b[1]));
}
__device__ __forceinline__ uint32_t bfx2(float lo, float hi) {   // low half = lo
    uint32_t r;
    asm("cvt.rn.bf16x2.f32 %0, %1, %2;" : "=r"(r) : "f"(hi), "f"(lo));
    return r;
}

// ---------------------------------------------------------------------------
// smem regions (bytes). 2 samples per CTA.
//  SM_X  : x tile 128 x 264 bf16 (stride 528) -> x2 -> t3
//  SM_QP : Q tile 128 x 528B -> P tiles 8 x (64 x 72 bf16, stride 144)
//  SM_KV : K tile 128 x 528B -> VT 2 x (256 ch x 72 bf16, stride 144)
// ---------------------------------------------------------------------------
#define SM_X    0        // 67584
#define SM_QP   67584    // 73728
#define SM_KV   141312   // 73728
#define SM_BIAS 215040   // 5120
#define SMEM_TOTAL 220160

#define NT 512   // 16 warps

// m128 x n256 x k256 GEMM, 16 warps: warp (mh = w>>3, nq = w&7) -> m64 x n32.
__device__ __forceinline__ void mma_gemm(uint32_t aBase, const uint4* __restrict__ Wf,
                                         float acc[4][4][4])
{
    #pragma unroll
    for (int mf = 0; mf < 4; mf++)
        #pragma unroll
        for (int nf = 0; nf < 4; nf++)
            #pragma unroll
            for (int q = 0; q < 4; q++) acc[mf][nf][q] = 0.0f;

    uint4 breg[2][4];
    #pragma unroll
    for (int nf = 0; nf < 4; nf++) breg[0][nf] = __ldg(Wf + nf * 256);

    #pragma unroll
    for (int kp = 0; kp < 8; kp++) {
        const int cur = kp & 1;
        if (kp < 7) {
            #pragma unroll
            for (int nf = 0; nf < 4; nf++)
                breg[cur ^ 1][nf] = __ldg(Wf + nf * 256 + (kp + 1) * 32);
        }
        #pragma unroll
        for (int sub = 0; sub < 2; sub++) {
            uint32_t a[4][4];
            #pragma unroll
            for (int mf = 0; mf < 4; mf++)
                ldsm4(a[mf], aBase + (uint32_t)(mf * 16 * 528 + (2*kp + sub) * 32));
            #pragma unroll
            for (int nf = 0; nf < 4; nf++) {
                uint32_t b[2];
                b[0] = sub ? breg[cur][nf].z : breg[cur][nf].x;
                b[1] = sub ? breg[cur][nf].w : breg[cur][nf].y;
                #pragma unroll
                for (int mf = 0; mf < 4; mf++) mma16816(acc[mf][nf], a[mf], b);
            }
        }
    }
}

__global__ __launch_bounds__(NT, 1) void irmb_kernel(
    const float* __restrict__ x, float* __restrict__ out)
{
    extern __shared__ char sm[];
    const uint32_t sb = s2u(sm);
    const int tid = threadIdx.x, w = tid >> 5, lane = tid & 31;
    const int s0 = blockIdx.x * 2;

    float* sBias = (float*)(sm + SM_BIAS);
    const float* xb = x + (size_t)s0 * SMP;
    float* ob = out + (size_t)s0 * SMP;
    float* Rb = g_R[s0];   // 2 samples contiguous

    // zero X tile (incl. pad rows), load biases
    {
        uint32_t* z = (uint32_t*)(sm + SM_X);
        for (int i = tid; i < 16896; i += NT) z[i] = 0;
        const float* gb = (const float*)g_b;
        for (int i = tid; i < 1280; i += NT) sBias[i] = gb[i];
    }
    __syncthreads();
    for (int i = tid; i < 2 * SMP; i += NT) {
        int s = i / SMP, j = i - s * SMP;
        int lr = j >> 8, c = j & 255;
        *(__nv_bfloat16*)(sm + SM_X + (s * 64 + lr) * 528 + c * 2) =
            __float2bfloat16(xb[i]);
    }
    __syncthreads();

    // lane constants
    const int gq = lane >> 3, iq = lane & 7;
    const uint32_t aoff  = (uint32_t)((iq + (gq & 1) * 8) * 528 + ((gq >> 1) * 8) * 2);
    const uint32_t aoffP = (uint32_t)((iq + (gq & 1) * 8) * 144 + ((gq >> 1) * 8) * 2);
    const int r0 = lane >> 2, c0 = 2 * (lane & 3);
    const int mh = w >> 3, nq = w & 7;
    const uint32_t aG = sb + SM_X + (uint32_t)(mh * 64 * 528) + aoff;
    const uint4* W4 = (const uint4*)g_Wbf;
    const int wfoff = nq * 1024 + lane;
    const int sA = w >> 3, hA = (w >> 1) & 3, mfsA = w & 1;

    float acc[4][4][4];

    // ---- Q -> SM_QP ----
    mma_gemm(aG, W4 + wfoff, acc);
    #pragma unroll
    for (int mf = 0; mf < 4; mf++)
        #pragma unroll
        for (int nf = 0; nf < 4; nf++)
            #pragma unroll
            for (int rr = 0; rr < 2; rr++) {
                int r = mh * 64 + mf * 16 + r0 + rr * 8;
                int c = nq * 32 + nf * 8 + c0;
                *(uint32_t*)(sm + SM_QP + r * 528 + c * 2) =
                    bfx2(acc[mf][nf][rr*2] + sBias[c], acc[mf][nf][rr*2+1] + sBias[c+1]);
            }

    // ---- K -> SM_KV ----
    mma_gemm(aG, W4 + W_MAT_U4 + wfoff, acc);
    #pragma unroll
    for (int mf = 0; mf < 4; mf++)
        #pragma unroll
        for (int nf = 0; nf < 4; nf++)
            #pragma unroll
            for (int rr = 0; rr < 2; rr++) {
                int r = mh * 64 + mf * 16 + r0 + rr * 8;
                int c = nq * 32 + nf * 8 + c0;
                *(uint32_t*)(sm + SM_KV + r * 528 + c * 2) =
                    bfx2(acc[mf][nf][rr*2] + sBias[256+c], acc[mf][nf][rr*2+1] + sBias[256+c+1]);
            }
    __syncthreads();

    // ---- scores: warp (sA, hA, mfsA): m32 query rows x 56 keys ----
    float sc[2][7][4];
    {
        #pragma unroll
        for (int mf = 0; mf < 2; mf++)
            #pragma unroll
            for (int nf = 0; nf < 7; nf++)
                #pragma unroll
                for (int q = 0; q < 4; q++) sc[mf][nf][q] = 0.0f;

        uint32_t qbase = sb + SM_QP + (uint32_t)((sA * 64 + mfsA * 32) * 528)
                       + aoff + (uint32_t)(hA * 128);
        uint32_t kb = sb + SM_KV + (uint32_t)((sA * 64 + (lane & 7)) * 528)
                    + (uint32_t)(hA * 128) + (uint32_t)(((lane >> 3) & 1) * 16);
        #pragma unroll
        for (int ks = 0; ks < 4; ks++) {
            uint32_t a[2][4];
            ldsm4(a[0], qbase + ks * 32);
            ldsm4(a[1], qbase + 16 * 528 + ks * 32);
            #pragma unroll
            for (int nf = 0; nf < 7; nf++) {
                uint32_t b[2];
                ldsm2(b, kb + (uint32_t)(nf * 8 * 528) + ks * 32);
                mma16816(sc[0][nf], a[0], b);
                mma16816(sc[1][nf], a[1], b);
            }
        }
    }
    __syncthreads();   // all Q/K reads done

    // ---- softmax (regs) + P store (overwrites Q region) ----
    #pragma unroll
    for (int mf = 0; mf < 2; mf++)
        #pragma unroll
        for (int half = 0; half < 2; half++) {
            int lr = mfsA * 32 + mf * 16 + half * 8 + r0;
            float vv[14];
            float m = -1e30f;
            #pragma unroll
            for (int nf = 0; nf < 7; nf++)
                #pragma unroll
                for (int j = 0; j < 2; j++) {
                    int kk = nf * 8 + c0 + j;
                    float s = (kk < NTOK) ? sc[mf][nf][half*2 + j] * 0.125f : -1e30f;
                    vv[nf*2 + j] = s;
                    m = fmaxf(m, s);
                }
            m = fmaxf(m, __shfl_xor_sync(0xFFFFFFFFu, m, 1));
            m = fmaxf(m, __shfl_xor_sync(0xFFFFFFFFu, m, 2));
            float sum = 0.0f;
            #pragma unroll
            for (int t = 0; t < 14; t++) {
                float e = (vv[t] > -1e29f) ? __expf(vv[t] - m) : 0.0f;
                vv[t] = e; sum += e;
            }
            sum += __shfl_xor_sync(0xFFFFFFFFu, sum, 1);
            sum += __shfl_xor_sync(0xFFFFFFFFu, sum, 2);
            float inv = 1.0f / sum;
            char* prow = sm + SM_QP + (sA * 4 + hA) * 9216 + lr * 144;
            #pragma unroll
            for (int nf = 0; nf < 7; nf++) {
                uint32_t pk = (lr < NTOK) ? bfx2(vv[nf*2] * inv, vv[nf*2+1] * inv) : 0u;
                *(uint32_t*)(prow + (nf * 8 + c0) * 2) = pk;
            }
            *(uint32_t*)(prow + (56 + c0) * 2) = 0u;
        }

    // ---- V GEMM (reads X); epilogue -> VT (SM_KV) + g_R.
    //      lr >= NTOK rows: write bf16 ZEROS into VT (kills stale-NaN 0*x) ----
    mma_gemm(aG, W4 + 2 * W_MAT_U4 + wfoff, acc);
    #pragma unroll
    for (int mf = 0; mf < 4; mf++)
        #pragma unroll
        for (int rr = 0; rr < 2; rr++) {
            int lr = mf * 16 + r0 + rr * 8;      // sample = mh
            if (lr < NTOK) {
                const float* xs = xb + mh * SMP + lr * 256;
                float2 xv[4];
                #pragma unroll
                for (int nf = 0; nf < 4; nf++)
                    xv[nf] = __ldg((const float2*)(xs + nq * 32 + nf * 8 + c0));
                #pragma unroll
                for (int nf = 0; nf < 4; nf++) {
                    int c = nq * 32 + nf * 8 + c0;
                    float v0 = (acc[mf][nf][rr*2]   + sBias[512+c])   * 0.1f + xv[nf].x * 0.95f;
                    float v1 = (acc[mf][nf][rr*2+1] + sBias[512+c+1]) * 0.1f + xv[nf].y * 0.95f;
                    *(float2*)(Rb + mh * SMP + lr * 256 + c) = make_float2(v0, v1);
                    *(__nv_bfloat16*)(sm + SM_KV + mh * 36864 + c * 144 + lr * 2)       = __float2bfloat16(v0);
                    *(__nv_bfloat16*)(sm + SM_KV + mh * 36864 + (c + 1) * 144 + lr * 2) = __float2bfloat16(v1);
                }
            } else {
                const __nv_bfloat16 z = __float2bfloat16(0.0f);
                #pragma unroll
                for (int nf = 0; nf < 4; nf++) {
                    int c = nq * 32 + nf * 8 + c0;
                    *(__nv_bfloat16*)(sm + SM_KV + mh * 36864 + c * 144 + lr * 2)       = z;
                    *(__nv_bfloat16*)(sm + SM_KV + mh * 36864 + (c + 1) * 144 + lr * 2) = z;
                }
            }
        }
    __syncthreads();   // P + VT complete

    // ---- PV: warp (sA, hA, mfsA): m32 rows x n64 head cols ----
    {
        float pa[2][8][4];
        #pragma unroll
        for (int mf = 0; mf < 2; mf++)
            #pragma unroll
            for (int nf = 0; nf < 8; nf++)
                #pragma unroll
                for (int q = 0; q < 4; q++) pa[mf][nf][q] = 0.0f;

        uint32_t pbase = sb + SM_QP + (uint32_t)((sA * 4 + hA) * 9216 + mfsA * 32 * 144) + aoffP;
        uint32_t vtb = sb + SM_KV + (uint32_t)(sA * 36864)
                     + (uint32_t)((hA * 64 + (lane & 7)) * 144)
                     + (uint32_t)(((lane >> 3) & 1) * 16);
        #pragma unroll
        for (int ks = 0; ks < 4; ks++) {
            uint32_t a[2][4];
            ldsm4(a[0], pbase + ks * 32);
            ldsm4(a[1], pbase + 16 * 144 + ks * 32);
            #pragma unroll
            for (int nf = 0; nf < 8; nf++) {
                uint32_t b[2];
                ldsm2(b, vtb + (uint32_t)(nf * 8 * 144) + ks * 32);
                mma16816(pa[0][nf], a[0], b);
                mma16816(pa[1][nf], a[1], b);
            }
        }
        #pragma unroll
        for (int mf = 0; mf < 2; mf++)
            #pragma unroll
            for (int rr = 0; rr < 2; rr++) {
                int lr = mfsA * 32 + mf * 16 + rr * 8 + r0;
                int rG = sA * 64 + lr;
                if (lr < NTOK) {
                    float2 rv[8];
                    #pragma unroll
                    for (int nf = 0; nf < 8; nf++)
                        rv[nf] = *(const float2*)(Rb + sA * SMP + lr * 256 + hA * 64 + nf * 8 + c0);
                    #pragma unroll
                    for (int nf = 0; nf < 8; nf++) {
                        int c = hA * 64 + nf * 8 + c0;
                        float a0 = pa[mf][nf][rr*2]   * 0.1f + rv[nf].x * 0.95f;
                        float a1 = pa[mf][nf][rr*2+1] * 0.1f + rv[nf].y * 0.95f;
                        *(float2*)(Rb + sA * SMP + lr * 256 + c) = make_float2(a0, a1);
                        *(uint32_t*)(sm + SM_X + rG * 528 + c * 2) = bfx2(a0, a1);
                    }
                } else {
                    #pragma unroll
                    for (int nf = 0; nf < 8; nf++) {
                        int c = hA * 64 + nf * 8 + c0;
                        *(uint32_t*)(sm + SM_X + rG * 528 + c * 2) = 0u;
                    }
                }
            }
    }
    __syncthreads();

    // ---- FFN in ----
    mma_gemm(aG, W4 + 3 * W_MAT_U4 + wfoff, acc);
    __syncthreads();           // x2 reads done
    #pragma unroll
    for (int mf = 0; mf < 4; mf++)
        #pragma unroll
        for (int rr = 0; rr < 2; rr++) {
            int lr = mf * 16 + r0 + rr * 8;
            int rG = mh * 64 + lr;
            if (lr < NTOK) {
                float2 rv[4];
                #pragma unroll
                for (int nf = 0; nf < 4; nf++)
                    rv[nf] = *(const float2*)(Rb + mh * SMP + lr * 256 + nq * 32 + nf * 8 + c0);
                #pragma unroll
                for (int nf = 0; nf < 4; nf++) {
                    int c = nq * 32 + nf * 8 + c0;
                    float t2a = (acc[mf][nf][rr*2]   + sBias[768+c])   * 0.1f + rv[nf].x * 0.95f;
                    float t2b = (acc[mf][nf][rr*2+1] + sBias[768+c+1]) * 0.1f + rv[nf].y * 0.95f;
                    float t3a = (1.0f/(1.0f + __expf(-t2a)) - 0.5f) * 0.1f + t2a * 0.95f;
                    float t3b = (1.0f/(1.0f + __expf(-t2b)) - 0.5f) * 0.1f + t2b * 0.95f;
                    *(float2*)(Rb + mh * SMP + lr * 256 + c) = make_float2(t3a, t3b);
                    *(uint32_t*)(sm + SM_X + rG * 528 + c * 2) = bfx2(t3a, t3b);
                }
            } else {
                #pragma unroll
                for (int nf = 0; nf < 4; nf++) {
                    int c = nq * 32 + nf * 8 + c0;
                    *(uint32_t*)(sm + SM_X + rG * 528 + c * 2) = 0u;
                }
            }
        }
    __syncthreads();

    // ---- FFN out ----
    mma_gemm(aG, W4 + 4 * W_MAT_U4 + wfoff, acc);
    #pragma unroll
    for (int mf = 0; mf < 4; mf++)
        #pragma unroll
        for (int rr = 0; rr < 2; rr++) {
            int lr = mf * 16 + r0 + rr * 8;
            if (lr < NTOK) {
                float2 rv[4];
                #pragma unroll
                for (int nf = 0; nf < 4; nf++)
                    rv[nf] = *(const float2*)(Rb + mh * SMP + lr * 256 + nq * 32 + nf * 8 + c0);
                #pragma unroll
                for (int nf = 0; nf < 4; nf++) {
                    int c = nq * 32 + nf * 8 + c0;
                    float o0 = (acc[mf][nf][rr*2]   + sBias[1024+c])   * 0.1f + rv[nf].x * 0.95f;
                    float o1 = (acc[mf][nf][rr*2+1] + sBias[1024+c+1]) * 0.1f + rv[nf].y * 0.95f;
                    *(float2*)(ob + mh * SMP + lr * 256 + c) = make_float2(o0, o1);
                }
            }
        }
}

// ---------------------------------------------------------------------------
extern "C" void kernel_launch(void* const* d_in, const int* in_sizes, int n_in,
                              void* d_out, int out_size)
{
    std_kernel<<<5 * DIM + 5, 256>>>(
        (const float*)d_in[1], (const float*)d_in[2],
        (const float*)d_in[3], (const float*)d_in[4],
        (const float*)d_in[5], (const float*)d_in[6],
        (const float*)d_in[7], (const float*)d_in[8],
        (const float*)d_in[9], (const float*)d_in[10]);

    cudaFuncSetAttribute(irmb_kernel,
                         cudaFuncAttributeMaxDynamicSharedMemorySize, SMEM_TOTAL);
    irmb_kernel<<<NB / 2, NT, SMEM_TOTAL>>>((const float*)d_in[0], (float*)d_out);
}

// round 13
// speedup vs baseline: 1.2823x; 1.0416x over previous
#include <cuda_runtime.h>
#include <cuda_bf16.h>
#include <math.h>
#include <stdint.h>

#define DIM  256
#define NH   4
#define HC   64
#define NTOK 49
#define NB   4096
#define SMP  12544   // NTOK*DIM

// Standardized weights in ks-paired mma-FRAGMENT order (uint4 granularity):
// uint4 index = (nblk*8 + kp)*32 + lane (per matrix), matrices contiguous.
__device__ __align__(16) __nv_bfloat16 g_Wbf[5][DIM * DIM];
__device__ float g_b[5][DIM];
// fp32 V' residual scratch per sample (only surviving gmem residual stream)
__device__ float g_R[NB][SMP];

#define W_MAT_U4 8192   // uint4 per 256x256 bf16 matrix

// ---------------------------------------------------------------------------
// Prologue: weight standardization -> ks-paired fragment-ordered bf16
// ---------------------------------------------------------------------------
__global__ __launch_bounds__(256) void std_kernel(
    const float* __restrict__ qw, const float* __restrict__ qb,
    const float* __restrict__ kw, const float* __restrict__ kb,
    const float* __restrict__ vw, const float* __restrict__ vb,
    const float* __restrict__ fiw, const float* __restrict__ fib,
    const float* __restrict__ fow, const float* __restrict__ fob)
{
    const float* wptr[5] = {qw, kw, vw, fiw, fow};
    const float* bptr[5] = {qb, kb, vb, fib, fob};
    __shared__ float s_sum[8], s_sq[8];
    int bx = blockIdx.x, t = threadIdx.x;

    float val;
    if (bx < 5 * DIM) val = wptr[bx >> 8][(bx & 255) * DIM + t];
    else              val = bptr[bx - 5 * DIM][t];

    float s = val, q = val * val;
    #pragma unroll
    for (int o = 16; o > 0; o >>= 1) {
        s += __shfl_xor_sync(0xFFFFFFFFu, s, o);
        q += __shfl_xor_sync(0xFFFFFFFFu, q, o);
    }
    if ((t & 31) == 0) { s_sum[t >> 5] = s; s_sq[t >> 5] = q; }
    __syncthreads();
    int h = t >> 6;
    float sum = s_sum[2*h] + s_sum[2*h+1];
    float sq  = s_sq [2*h] + s_sq [2*h+1];
    float mean = sum * (1.0f/64.0f);
    float var  = fmaxf(sq * (1.0f/64.0f) - mean*mean, 0.0f);
    float r    = (val - mean) / (sqrtf(var) * 16.0f);

    if (bx < 5 * DIM) {
        int m = bx >> 8, k = bx & 255, c = t;
        int kp   = k >> 5;
        int kodd = (k >> 4) & 1;
        int half = (k >> 3) & 1;
        int pos2 = (k >> 1) & 3;
        int par  = k & 1;
        int lane = (c & 7) * 4 + pos2;
        int nblk = c >> 3;
        size_t idx = ((size_t)(((nblk * 8 + kp) * 32 + lane)) << 3)
                   + (size_t)(kodd * 4 + half * 2 + par);
        ((__nv_bfloat16*)g_Wbf)[(size_t)m * DIM * DIM + idx] = __float2bfloat16(r);
    } else {
        g_b[bx - 5 * DIM][t] = r;
    }
}

// ---------------------------------------------------------------------------
// PTX helpers
// ---------------------------------------------------------------------------
__device__ __forceinline__ uint32_t s2u(const void* p) {
    uint32_t a;
    asm("{ .reg .u64 t; cvta.to.shared.u64 t, %1; cvt.u32.u64 %0, t; }" : "=r"(a) : "l"(p));
    return a;
}
__device__ __forceinline__ void ldsm4(uint32_t* r, uint32_t a) {
    asm volatile("ldmatrix.sync.aligned.m8n8.x4.shared.b16 {%0,%1,%2,%3}, [%4];"
                 : "=r"(r[0]), "=r"(r[1]), "=r"(r[2]), "=r"(r[3]) : "r"(a));
}
__device__ __forceinline__ void ldsm2(uint32_t* r, uint32_t a) {
    asm volatile("ldmatrix.sync.aligned.m8n8.x2.shared.b16 {%0,%1}, [%2];"
                 : "=r"(r[0]), "=r"(r[1]) : "r"(a));
}
__device__ __forceinline__ void mma16816(float* d, const uint32_t* a, const uint32_t* b) {
    asm volatile("mma.sync.aligned.m16n8k16.row.col.f32.bf16.bf16.f32 "
                 "{%0,%1,%2,%3}, {%4,%5,%6,%7}, {%8,%9}, {%0,%1,%2,%3};"
                 : "+f"(d[0]), "+f"(d[1]), "+f"(d[2]), "+f"(d[3])
                 : "r"(a[0]), "r"(a[1]), "r"(a[2]), "r"(a[3]), "r"(b[0]), "r"(b[1]));
}
__device__ __forceinline__ uint32_t bfx2(float lo, float hi) {   // low half = lo
    uint32_t r;
    asm("cvt.rn.bf16x2.f32 %0, %1, %2;" : "=r"(r) : "f"(hi), "f"(lo));
    return r;
}

// ---------------------------------------------------------------------------
// smem regions (bytes). 2 samples per CTA.
//  SM_X  : x tile 128 x 264 bf16 (stride 528) -> x2 -> t3 (bf16 operand tiles)
//  SM_QP : Q tile 128 x 528B -> P tiles 8 x (64 x 72 bf16, stride 144)
//          -> (after PV MMAs) x2/t3 fp32 buffer [128][260] (spans into SM_KV)
//  SM_KV : K tile 128 x 528B -> VT 2 x (256 ch x 72 bf16, stride 144)
// ---------------------------------------------------------------------------
#define SM_X    0        // 67584
#define SM_QP   67584    // 73728
#define SM_KV   141312   // 73728
#define SM_BIAS 215040   // 5120
#define SMEM_TOTAL 220160

// fp32 residual buffer aliasing SM_QP..: row stride 1040 B (260 floats, 4-bank shift)
#define SM_F32  SM_QP
#define F32ST   1040     // bytes per row; 128 rows = 133120 B, ends at 200704 < 215040

#define NT 512   // 16 warps

// m128 x n256 x k256 GEMM, 16 warps: warp (mh = w>>3, nq = w&7) -> m64 x n32.
__device__ __forceinline__ void mma_gemm(uint32_t aBase, const uint4* __restrict__ Wf,
                                         float acc[4][4][4])
{
    #pragma unroll
    for (int mf = 0; mf < 4; mf++)
        #pragma unroll
        for (int nf = 0; nf < 4; nf++)
            #pragma unroll
            for (int q = 0; q < 4; q++) acc[mf][nf][q] = 0.0f;

    uint4 breg[2][4];
    #pragma unroll
    for (int nf = 0; nf < 4; nf++) breg[0][nf] = __ldg(Wf + nf * 256);

    #pragma unroll
    for (int kp = 0; kp < 8; kp++) {
        const int cur = kp & 1;
        if (kp < 7) {
            #pragma unroll
            for (int nf = 0; nf < 4; nf++)
                breg[cur ^ 1][nf] = __ldg(Wf + nf * 256 + (kp + 1) * 32);
        }
        #pragma unroll
        for (int sub = 0; sub < 2; sub++) {
            uint32_t a[4][4];
            #pragma unroll
            for (int mf = 0; mf < 4; mf++)
                ldsm4(a[mf], aBase + (uint32_t)(mf * 16 * 528 + (2*kp + sub) * 32));
            #pragma unroll
            for (int nf = 0; nf < 4; nf++) {
                uint32_t b[2];
                b[0] = sub ? breg[cur][nf].z : breg[cur][nf].x;
                b[1] = sub ? breg[cur][nf].w : breg[cur][nf].y;
                #pragma unroll
                for (int mf = 0; mf < 4; mf++) mma16816(acc[mf][nf], a[mf], b);
            }
        }
    }
}

__global__ __launch_bounds__(NT, 1) void irmb_kernel(
    const float* __restrict__ x, float* __restrict__ out)
{
    extern __shared__ char sm[];
    const uint32_t sb = s2u(sm);
    const int tid = threadIdx.x, w = tid >> 5, lane = tid & 31;
    const int s0 = blockIdx.x * 2;

    float* sBias = (float*)(sm + SM_BIAS);
    const float* xb = x + (size_t)s0 * SMP;
    float* ob = out + (size_t)s0 * SMP;
    float* Rb = g_R[s0];   // 2 samples contiguous (V' residual only)

    // zero X tile (incl. pad rows), load biases
    {
        uint32_t* z = (uint32_t*)(sm + SM_X);
        for (int i = tid; i < 16896; i += NT) z[i] = 0;
        const float* gb = (const float*)g_b;
        for (int i = tid; i < 1280; i += NT) sBias[i] = gb[i];
    }
    __syncthreads();
    for (int i = tid; i < 2 * SMP; i += NT) {
        int s = i / SMP, j = i - s * SMP;
        int lr = j >> 8, c = j & 255;
        *(__nv_bfloat16*)(sm + SM_X + (s * 64 + lr) * 528 + c * 2) =
            __float2bfloat16(xb[i]);
    }
    __syncthreads();

    // lane constants
    const int gq = lane >> 3, iq = lane & 7;
    const uint32_t aoff  = (uint32_t)((iq + (gq & 1) * 8) * 528 + ((gq >> 1) * 8) * 2);
    const uint32_t aoffP = (uint32_t)((iq + (gq & 1) * 8) * 144 + ((gq >> 1) * 8) * 2);
    const int r0 = lane >> 2, c0 = 2 * (lane & 3);
    const int mh = w >> 3, nq = w & 7;
    const uint32_t aG = sb + SM_X + (uint32_t)(mh * 64 * 528) + aoff;
    const uint4* W4 = (const uint4*)g_Wbf;
    const int wfoff = nq * 1024 + lane;
    const int sA = w >> 3, hA = (w >> 1) & 3, mfsA = w & 1;

    float acc[4][4][4];

    // ---- Q -> SM_QP ----
    mma_gemm(aG, W4 + wfoff, acc);
    #pragma unroll
    for (int mf = 0; mf < 4; mf++)
        #pragma unroll
        for (int nf = 0; nf < 4; nf++)
            #pragma unroll
            for (int rr = 0; rr < 2; rr++) {
                int r = mh * 64 + mf * 16 + r0 + rr * 8;
                int c = nq * 32 + nf * 8 + c0;
                *(uint32_t*)(sm + SM_QP + r * 528 + c * 2) =
                    bfx2(acc[mf][nf][rr*2] + sBias[c], acc[mf][nf][rr*2+1] + sBias[c+1]);
            }

    // ---- K -> SM_KV ----
    mma_gemm(aG, W4 + W_MAT_U4 + wfoff, acc);
    #pragma unroll
    for (int mf = 0; mf < 4; mf++)
        #pragma unroll
        for (int nf = 0; nf < 4; nf++)
            #pragma unroll
            for (int rr = 0; rr < 2; rr++) {
                int r = mh * 64 + mf * 16 + r0 + rr * 8;
                int c = nq * 32 + nf * 8 + c0;
                *(uint32_t*)(sm + SM_KV + r * 528 + c * 2) =
                    bfx2(acc[mf][nf][rr*2] + sBias[256+c], acc[mf][nf][rr*2+1] + sBias[256+c+1]);
            }
    __syncthreads();

    // ---- scores: warp (sA, hA, mfsA): m32 query rows x 56 keys ----
    float sc[2][7][4];
    {
        #pragma unroll
        for (int mf = 0; mf < 2; mf++)
            #pragma unroll
            for (int nf = 0; nf < 7; nf++)
                #pragma unroll
                for (int q = 0; q < 4; q++) sc[mf][nf][q] = 0.0f;

        uint32_t qbase = sb + SM_QP + (uint32_t)((sA * 64 + mfsA * 32) * 528)
                       + aoff + (uint32_t)(hA * 128);
        uint32_t kb = sb + SM_KV + (uint32_t)((sA * 64 + (lane & 7)) * 528)
                    + (uint32_t)(hA * 128) + (uint32_t)(((lane >> 3) & 1) * 16);
        #pragma unroll
        for (int ks = 0; ks < 4; ks++) {
            uint32_t a[2][4];
            ldsm4(a[0], qbase + ks * 32);
            ldsm4(a[1], qbase + 16 * 528 + ks * 32);
            #pragma unroll
            for (int nf = 0; nf < 7; nf++) {
                uint32_t b[2];
                ldsm2(b, kb + (uint32_t)(nf * 8 * 528) + ks * 32);
                mma16816(sc[0][nf], a[0], b);
                mma16816(sc[1][nf], a[1], b);
            }
        }
    }
    __syncthreads();   // all Q/K reads done

    // ---- softmax (regs) + P store (overwrites Q region) ----
    #pragma unroll
    for (int mf = 0; mf < 2; mf++)
        #pragma unroll
        for (int half = 0; half < 2; half++) {
            int lr = mfsA * 32 + mf * 16 + half * 8 + r0;
            float vv[14];
            float m = -1e30f;
            #pragma unroll
            for (int nf = 0; nf < 7; nf++)
                #pragma unroll
                for (int j = 0; j < 2; j++) {
                    int kk = nf * 8 + c0 + j;
                    float s = (kk < NTOK) ? sc[mf][nf][half*2 + j] * 0.125f : -1e30f;
                    vv[nf*2 + j] = s;
                    m = fmaxf(m, s);
                }
            m = fmaxf(m, __shfl_xor_sync(0xFFFFFFFFu, m, 1));
            m = fmaxf(m, __shfl_xor_sync(0xFFFFFFFFu, m, 2));
            float sum = 0.0f;
            #pragma unroll
            for (int t = 0; t < 14; t++) {
                float e = (vv[t] > -1e29f) ? __expf(vv[t] - m) : 0.0f;
                vv[t] = e; sum += e;
            }
            sum += __shfl_xor_sync(0xFFFFFFFFu, sum, 1);
            sum += __shfl_xor_sync(0xFFFFFFFFu, sum, 2);
            float inv = 1.0f / sum;
            char* prow = sm + SM_QP + (sA * 4 + hA) * 9216 + lr * 144;
            #pragma unroll
            for (int nf = 0; nf < 7; nf++) {
                uint32_t pk = (lr < NTOK) ? bfx2(vv[nf*2] * inv, vv[nf*2+1] * inv) : 0u;
                *(uint32_t*)(prow + (nf * 8 + c0) * 2) = pk;
            }
            *(uint32_t*)(prow + (56 + c0) * 2) = 0u;
        }

    // ---- V GEMM (reads X); epilogue -> VT (SM_KV) + g_R.
    //      lr >= NTOK rows: bf16 ZEROS into VT ----
    mma_gemm(aG, W4 + 2 * W_MAT_U4 + wfoff, acc);
    #pragma unroll
    for (int mf = 0; mf < 4; mf++)
        #pragma unroll
        for (int rr = 0; rr < 2; rr++) {
            int lr = mf * 16 + r0 + rr * 8;      // sample = mh
            if (lr < NTOK) {
                const float* xs = xb + mh * SMP + lr * 256;
                float2 xv[4];
                #pragma unroll
                for (int nf = 0; nf < 4; nf++)
                    xv[nf] = __ldg((const float2*)(xs + nq * 32 + nf * 8 + c0));
                #pragma unroll
                for (int nf = 0; nf < 4; nf++) {
                    int c = nq * 32 + nf * 8 + c0;
                    float v0 = (acc[mf][nf][rr*2]   + sBias[512+c])   * 0.1f + xv[nf].x * 0.95f;
                    float v1 = (acc[mf][nf][rr*2+1] + sBias[512+c+1]) * 0.1f + xv[nf].y * 0.95f;
                    *(float2*)(Rb + mh * SMP + lr * 256 + c) = make_float2(v0, v1);
                    *(__nv_bfloat16*)(sm + SM_KV + mh * 36864 + c * 144 + lr * 2)       = __float2bfloat16(v0);
                    *(__nv_bfloat16*)(sm + SM_KV + mh * 36864 + (c + 1) * 144 + lr * 2) = __float2bfloat16(v1);
                }
            } else {
                const __nv_bfloat16 z = __float2bfloat16(0.0f);
                #pragma unroll
                for (int nf = 0; nf < 4; nf++) {
                    int c = nq * 32 + nf * 8 + c0;
                    *(__nv_bfloat16*)(sm + SM_KV + mh * 36864 + c * 144 + lr * 2)       = z;
                    *(__nv_bfloat16*)(sm + SM_KV + mh * 36864 + (c + 1) * 144 + lr * 2) = z;
                }
            }
        }
    __syncthreads();   // P + VT complete

    // ---- PV MMAs: warp (sA, hA, mfsA): m32 rows x n64 head cols ----
    {
        float pa[2][8][4];
        #pragma unroll
        for (int mf = 0; mf < 2; mf++)
            #pragma unroll
            for (int nf = 0; nf < 8; nf++)
                #pragma unroll
                for (int q = 0; q < 4; q++) pa[mf][nf][q] = 0.0f;

        uint32_t pbase = sb + SM_QP + (uint32_t)((sA * 4 + hA) * 9216 + mfsA * 32 * 144) + aoffP;
        uint32_t vtb = sb + SM_KV + (uint32_t)(sA * 36864)
                     + (uint32_t)((hA * 64 + (lane & 7)) * 144)
                     + (uint32_t)(((lane >> 3) & 1) * 16);
        #pragma unroll
        for (int ks = 0; ks < 4; ks++) {
            uint32_t a[2][4];
            ldsm4(a[0], pbase + ks * 32);
            ldsm4(a[1], pbase + 16 * 144 + ks * 32);
            #pragma unroll
            for (int nf = 0; nf < 8; nf++) {
                uint32_t b[2];
                ldsm2(b, vtb + (uint32_t)(nf * 8 * 144) + ks * 32);
                mma16816(pa[0][nf], a[0], b);
                mma16816(pa[1][nf], a[1], b);
            }
        }
        __syncthreads();   // ALL P/VT reads done; SM_QP/SM_KV free for fp32 x2

        // ---- PV epilogue: x2 = PV*0.1 + V'*0.95 -> fp32 smem + bf16 SM_X ----
        #pragma unroll
        for (int mf = 0; mf < 2; mf++)
            #pragma unroll
            for (int rr = 0; rr < 2; rr++) {
                int lr = mfsA * 32 + mf * 16 + rr * 8 + r0;
                int rG = sA * 64 + lr;
                if (lr < NTOK) {
                    float2 rv[8];
                    #pragma unroll
                    for (int nf = 0; nf < 8; nf++)
                        rv[nf] = *(const float2*)(Rb + sA * SMP + lr * 256 + hA * 64 + nf * 8 + c0);
                    #pragma unroll
                    for (int nf = 0; nf < 8; nf++) {
                        int c = hA * 64 + nf * 8 + c0;
                        float a0 = pa[mf][nf][rr*2]   * 0.1f + rv[nf].x * 0.95f;
                        float a1 = pa[mf][nf][rr*2+1] * 0.1f + rv[nf].y * 0.95f;
                        *(float2*)(sm + SM_F32 + rG * F32ST + c * 4) = make_float2(a0, a1);
                        *(uint32_t*)(sm + SM_X + rG * 528 + c * 2) = bfx2(a0, a1);
                    }
                } else {
                    #pragma unroll
                    for (int nf = 0; nf < 8; nf++) {
                        int c = hA * 64 + nf * 8 + c0;
                        *(uint32_t*)(sm + SM_X + rG * 528 + c * 2) = 0u;
                    }
                }
            }
    }
    __syncthreads();

    // ---- FFN in (reads bf16 x2 tile) ----
    mma_gemm(aG, W4 + 3 * W_MAT_U4 + wfoff, acc);
    __syncthreads();           // x2 reads done
    #pragma unroll
    for (int mf = 0; mf < 4; mf++)
        #pragma unroll
        for (int rr = 0; rr < 2; rr++) {
            int lr = mf * 16 + r0 + rr * 8;
            int rG = mh * 64 + lr;
            if (lr < NTOK) {
                float2 rv[4];
                #pragma unroll
                for (int nf = 0; nf < 4; nf++)
                    rv[nf] = *(const float2*)(sm + SM_F32 + rG * F32ST + (nq * 32 + nf * 8 + c0) * 4);
                #pragma unroll
                for (int nf = 0; nf < 4; nf++) {
                    int c = nq * 32 + nf * 8 + c0;
                    float t2a = (acc[mf][nf][rr*2]   + sBias[768+c])   * 0.1f + rv[nf].x * 0.95f;
                    float t2b = (acc[mf][nf][rr*2+1] + sBias[768+c+1]) * 0.1f + rv[nf].y * 0.95f;
                    float t3a = (1.0f/(1.0f + __expf(-t2a)) - 0.5f) * 0.1f + t2a * 0.95f;
                    float t3b = (1.0f/(1.0f + __expf(-t2b)) - 0.5f) * 0.1f + t2b * 0.95f;
                    *(float2*)(sm + SM_F32 + rG * F32ST + c * 4) = make_float2(t3a, t3b);
                    *(uint32_t*)(sm + SM_X + rG * 528 + c * 2) = bfx2(t3a, t3b);
                }
            } else {
                #pragma unroll
                for (int nf = 0; nf < 4; nf++) {
                    int c = nq * 32 + nf * 8 + c0;
                    *(uint32_t*)(sm + SM_X + rG * 528 + c * 2) = 0u;
                }
            }
        }
    __syncthreads();

    // ---- FFN out ----
    mma_gemm(aG, W4 + 4 * W_MAT_U4 + wfoff, acc);
    #pragma unroll
    for (int mf = 0; mf < 4; mf++)
        #pragma unroll
        for (int rr = 0; rr < 2; rr++) {
            int lr = mf * 16 + r0 + rr * 8;
            int rG = mh * 64 + lr;
            if (lr < NTOK) {
                float2 rv[4];
                #pragma unroll
                for (int nf = 0; nf < 4; nf++)
                    rv[nf] = *(const float2*)(sm + SM_F32 + rG * F32ST + (nq * 32 + nf * 8 + c0) * 4);
                #pragma unroll
                for (int nf = 0; nf < 4; nf++) {
                    int c = nq * 32 + nf * 8 + c0;
                    float o0 = (acc[mf][nf][rr*2]   + sBias[1024+c])   * 0.1f + rv[nf].x * 0.95f;
                    float o1 = (acc[mf][nf][rr*2+1] + sBias[1024+c+1]) * 0.1f + rv[nf].y * 0.95f;
                    *(float2*)(ob + mh * SMP + lr * 256 + c) = make_float2(o0, o1);
                }
            }
        }
}

// ---------------------------------------------------------------------------
extern "C" void kernel_launch(void* const* d_in, const int* in_sizes, int n_in,
                              void* d_out, int out_size)
{
    std_kernel<<<5 * DIM + 5, 256>>>(
        (const float*)d_in[1], (const float*)d_in[2],
        (const float*)d_in[3], (const float*)d_in[4],
        (const float*)d_in[5], (const float*)d_in[6],
        (const float*)d_in[7], (const float*)d_in[8],
        (const float*)d_in[9], (const float*)d_in[10]);

    cudaFuncSetAttribute(irmb_kernel,
                         cudaFuncAttributeMaxDynamicSharedMemorySize, SMEM_TOTAL);
    irmb_kernel<<<NB / 2, NT, SMEM_TOTAL>>>((const float*)d_in[0], (float*)d_out);
}

// round 14
// speedup vs baseline: 1.2908x; 1.0066x over previous
#include <cuda_runtime.h>
#include <cuda_bf16.h>
#include <math.h>
#include <stdint.h>

#define DIM  256
#define NH   4
#define HC   64
#define NTOK 49
#define NB   4096
#define SMP  12544   // NTOK*DIM

// Standardized weights in ks-paired mma-FRAGMENT order (uint4 granularity):
// uint4 index = (nblk*8 + kp)*32 + lane (per matrix), matrices contiguous.
__device__ __align__(16) __nv_bfloat16 g_Wbf[5][DIM * DIM];
__device__ float g_b[5][DIM];
// fp32 V' residual scratch per sample (only surviving gmem residual stream)
__device__ float g_R[NB][SMP];

#define W_MAT_U4 8192   // uint4 per 256x256 bf16 matrix

// ---------------------------------------------------------------------------
// Prologue: weight standardization -> ks-paired fragment-ordered bf16
// ---------------------------------------------------------------------------
__global__ __launch_bounds__(256) void std_kernel(
    const float* __restrict__ qw, const float* __restrict__ qb,
    const float* __restrict__ kw, const float* __restrict__ kb,
    const float* __restrict__ vw, const float* __restrict__ vb,
    const float* __restrict__ fiw, const float* __restrict__ fib,
    const float* __restrict__ fow, const float* __restrict__ fob)
{
    const float* wptr[5] = {qw, kw, vw, fiw, fow};
    const float* bptr[5] = {qb, kb, vb, fib, fob};
    __shared__ float s_sum[8], s_sq[8];
    int bx = blockIdx.x, t = threadIdx.x;

    float val;
    if (bx < 5 * DIM) val = wptr[bx >> 8][(bx & 255) * DIM + t];
    else              val = bptr[bx - 5 * DIM][t];

    float s = val, q = val * val;
    #pragma unroll
    for (int o = 16; o > 0; o >>= 1) {
        s += __shfl_xor_sync(0xFFFFFFFFu, s, o);
        q += __shfl_xor_sync(0xFFFFFFFFu, q, o);
    }
    if ((t & 31) == 0) { s_sum[t >> 5] = s; s_sq[t >> 5] = q; }
    __syncthreads();
    int h = t >> 6;
    float sum = s_sum[2*h] + s_sum[2*h+1];
    float sq  = s_sq [2*h] + s_sq [2*h+1];
    float mean = sum * (1.0f/64.0f);
    float var  = fmaxf(sq * (1.0f/64.0f) - mean*mean, 0.0f);
    float r    = (val - mean) / (sqrtf(var) * 16.0f);

    if (bx < 5 * DIM) {
        int m = bx >> 8, k = bx & 255, c = t;
        int kp   = k >> 5;
        int kodd = (k >> 4) & 1;
        int half = (k >> 3) & 1;
        int pos2 = (k >> 1) & 3;
        int par  = k & 1;
        int lane = (c & 7) * 4 + pos2;
        int nblk = c >> 3;
        size_t idx = ((size_t)(((nblk * 8 + kp) * 32 + lane)) << 3)
                   + (size_t)(kodd * 4 + half * 2 + par);
        ((__nv_bfloat16*)g_Wbf)[(size_t)m * DIM * DIM + idx] = __float2bfloat16(r);
    } else {
        g_b[bx - 5 * DIM][t] = r;
    }
}

// ---------------------------------------------------------------------------
// PTX helpers
// ---------------------------------------------------------------------------
__device__ __forceinline__ uint32_t s2u(const void* p) {
    uint32_t a;
    asm("{ .reg .u64 t; cvta.to.shared.u64 t, %1; cvt.u32.u64 %0, t; }" : "=r"(a) : "l"(p));
    return a;
}
__device__ __forceinline__ void ldsm4(uint32_t* r, uint32_t a) {
    asm volatile("ldmatrix.sync.aligned.m8n8.x4.shared.b16 {%0,%1,%2,%3}, [%4];"
                 : "=r"(r[0]), "=r"(r[1]), "=r"(r[2]), "=r"(r[3]) : "r"(a));
}
__device__ __forceinline__ void ldsm2(uint32_t* r, uint32_t a) {
    asm volatile("ldmatrix.sync.aligned.m8n8.x2.shared.b16 {%0,%1}, [%2];"
                 : "=r"(r[0]), "=r"(r[1]) : "r"(a));
}
__device__ __forceinline__ void mma16816(float* d, const uint32_t* a, const uint32_t* b) {
    asm volatile("mma.sync.aligned.m16n8k16.row.col.f32.bf16.bf16.f32 "
                 "{%0,%1,%2,%3}, {%4,%5,%6,%7}, {%8,%9}, {%0,%1,%2,%3};"
                 : "+f"(d[0]), "+f"(d[1]), "+f"(d[2]), "+f"(d[3])
                 : "r"(a[0]), "r"(a[1]), "r"(a[2]), "r"(a[3]), "r"(b[0]), "r"(b[1]));
}
__device__ __forceinline__ uint32_t bfx2(float lo, float hi) {   // low half = lo
    uint32_t r;
    asm("cvt.rn.bf16x2.f32 %0, %1, %2;" : "=r"(r) : "f"(hi), "f"(lo));
    return r;
}

// ---------------------------------------------------------------------------
// smem regions (bytes). 2 samples per CTA.
//  SM_X  : x tile 128 x 264 bf16 (stride 528) -> x2 -> t3 (bf16 operand tiles)
//  SM_QP : Q tile 128 x 528B -> P tiles 8 x (64 x 72 bf16, stride 144)
//          -> (after PV MMAs) x2/t3 fp32 buffer [128][260] (spans into SM_KV)
//  SM_KV : K tile 128 x 528B -> VT 2 x (256 ch x 72 bf16, stride 144)
// ---------------------------------------------------------------------------
#define SM_X    0        // 67584
#define SM_QP   67584    // 73728
#define SM_KV   141312   // 73728
#define SM_BIAS 215040   // 5120
#define SMEM_TOTAL 220160

// fp32 residual buffer aliasing SM_QP..: row stride 1040 B (260 floats)
#define SM_F32  SM_QP
#define F32ST   1040

#define NT 512   // 16 warps

// m128 x n256 x k256 GEMM, 16 warps: warp (mh = w>>3, nq = w&7) -> m64 x n32.
// A-fragment ping-pong (1 k-step ahead); B double-buffered at kp granularity.
__device__ __forceinline__ void mma_gemm(uint32_t aBase, const uint4* __restrict__ Wf,
                                         float acc[4][4][4])
{
    #pragma unroll
    for (int mf = 0; mf < 4; mf++)
        #pragma unroll
        for (int nf = 0; nf < 4; nf++)
            #pragma unroll
            for (int q = 0; q < 4; q++) acc[mf][nf][q] = 0.0f;

    uint4 breg[2][4];
    #pragma unroll
    for (int nf = 0; nf < 4; nf++) breg[0][nf] = __ldg(Wf + nf * 256);

    uint32_t a[2][4][4];
    #pragma unroll
    for (int mf = 0; mf < 4; mf++)
        ldsm4(a[0][mf], aBase + (uint32_t)(mf * 16 * 528));

    #pragma unroll
    for (int ks = 0; ks < 16; ks++) {
        const int kp  = ks >> 1, sub = ks & 1;
        const int cur = ks & 1;
        if (sub == 0 && kp < 7) {
            #pragma unroll
            for (int nf = 0; nf < 4; nf++)
                breg[(kp + 1) & 1][nf] = __ldg(Wf + nf * 256 + (kp + 1) * 32);
        }
        if (ks < 15) {
            #pragma unroll
            for (int mf = 0; mf < 4; mf++)
                ldsm4(a[cur ^ 1][mf], aBase + (uint32_t)(mf * 16 * 528 + (ks + 1) * 32));
        }
        #pragma unroll
        for (int nf = 0; nf < 4; nf++) {
            uint32_t b[2];
            b[0] = sub ? breg[kp & 1][nf].z : breg[kp & 1][nf].x;
            b[1] = sub ? breg[kp & 1][nf].w : breg[kp & 1][nf].y;
            #pragma unroll
            for (int mf = 0; mf < 4; mf++) mma16816(acc[mf][nf], a[cur][mf], b);
        }
    }
}

__global__ __launch_bounds__(NT, 1) void irmb_kernel(
    const float* __restrict__ x, float* __restrict__ out)
{
    extern __shared__ char sm[];
    const uint32_t sb = s2u(sm);
    const int tid = threadIdx.x, w = tid >> 5, lane = tid & 31;
    const int s0 = blockIdx.x * 2;

    float* sBias = (float*)(sm + SM_BIAS);
    const float* xb = x + (size_t)s0 * SMP;
    float* ob = out + (size_t)s0 * SMP;
    float* Rb = g_R[s0];

    // zero X tile (incl. pad rows), load biases
    {
        uint32_t* z = (uint32_t*)(sm + SM_X);
        for (int i = tid; i < 16896; i += NT) z[i] = 0;
        const float* gb = (const float*)g_b;
        for (int i = tid; i < 1280; i += NT) sBias[i] = gb[i];
    }
    __syncthreads();
    for (int i = tid; i < 2 * SMP; i += NT) {
        int s = i / SMP, j = i - s * SMP;
        int lr = j >> 8, c = j & 255;
        *(__nv_bfloat16*)(sm + SM_X + (s * 64 + lr) * 528 + c * 2) =
            __float2bfloat16(xb[i]);
    }
    __syncthreads();

    // lane constants
    const int gq = lane >> 3, iq = lane & 7;
    const uint32_t aoff  = (uint32_t)((iq + (gq & 1) * 8) * 528 + ((gq >> 1) * 8) * 2);
    const uint32_t aoffP = (uint32_t)((iq + (gq & 1) * 8) * 144 + ((gq >> 1) * 8) * 2);
    const int r0 = lane >> 2, c0 = 2 * (lane & 3);
    const int mh = w >> 3, nq = w & 7;
    const uint32_t aG = sb + SM_X + (uint32_t)(mh * 64 * 528) + aoff;
    const uint4* W4 = (const uint4*)g_Wbf;
    const int wfoff = nq * 1024 + lane;
    const int sA = w >> 3, hA = (w >> 1) & 3, mfsA = w & 1;

    float acc[4][4][4];

    // ---- Q -> SM_QP ----
    mma_gemm(aG, W4 + wfoff, acc);
    #pragma unroll
    for (int mf = 0; mf < 4; mf++)
        #pragma unroll
        for (int nf = 0; nf < 4; nf++)
            #pragma unroll
            for (int rr = 0; rr < 2; rr++) {
                int r = mh * 64 + mf * 16 + r0 + rr * 8;
                int c = nq * 32 + nf * 8 + c0;
                *(uint32_t*)(sm + SM_QP + r * 528 + c * 2) =
                    bfx2(acc[mf][nf][rr*2] + sBias[c], acc[mf][nf][rr*2+1] + sBias[c+1]);
            }

    // ---- K -> SM_KV (rows >= 56 per sample never read by scores: skip) ----
    mma_gemm(aG, W4 + W_MAT_U4 + wfoff, acc);
    #pragma unroll
    for (int mf = 0; mf < 4; mf++)
        #pragma unroll
        for (int nf = 0; nf < 4; nf++)
            #pragma unroll
            for (int rr = 0; rr < 2; rr++) {
                int lr = mf * 16 + r0 + rr * 8;
                if (lr < 56) {
                    int r = mh * 64 + lr;
                    int c = nq * 32 + nf * 8 + c0;
                    *(uint32_t*)(sm + SM_KV + r * 528 + c * 2) =
                        bfx2(acc[mf][nf][rr*2] + sBias[256+c], acc[mf][nf][rr*2+1] + sBias[256+c+1]);
                }
            }
    __syncthreads();

    // ---- scores: warp (sA, hA, mfsA): m32 query rows x 56 keys ----
    float sc[2][7][4];
    {
        #pragma unroll
        for (int mf = 0; mf < 2; mf++)
            #pragma unroll
            for (int nf = 0; nf < 7; nf++)
                #pragma unroll
                for (int q = 0; q < 4; q++) sc[mf][nf][q] = 0.0f;

        uint32_t qbase = sb + SM_QP + (uint32_t)((sA * 64 + mfsA * 32) * 528)
                       + aoff + (uint32_t)(hA * 128);
        uint32_t kb = sb + SM_KV + (uint32_t)((sA * 64 + (lane & 7)) * 528)
                    + (uint32_t)(hA * 128) + (uint32_t)(((lane >> 3) & 1) * 16);
        #pragma unroll
        for (int ks = 0; ks < 4; ks++) {
            uint32_t a[2][4];
            ldsm4(a[0], qbase + ks * 32);
            ldsm4(a[1], qbase + 16 * 528 + ks * 32);
            #pragma unroll
            for (int nf = 0; nf < 7; nf++) {
                uint32_t b[2];
                ldsm2(b, kb + (uint32_t)(nf * 8 * 528) + ks * 32);
                mma16816(sc[0][nf], a[0], b);
                mma16816(sc[1][nf], a[1], b);
            }
        }
    }
    __syncthreads();   // all Q/K reads done

    // ---- softmax (regs) + P store (overwrites Q region) ----
    #pragma unroll
    for (int mf = 0; mf < 2; mf++)
        #pragma unroll
        for (int half = 0; half < 2; half++) {
            int lr = mfsA * 32 + mf * 16 + half * 8 + r0;
            float vv[14];
            float m = -1e30f;
            #pragma unroll
            for (int nf = 0; nf < 7; nf++)
                #pragma unroll
                for (int j = 0; j < 2; j++) {
                    int kk = nf * 8 + c0 + j;
                    float s = (kk < NTOK) ? sc[mf][nf][half*2 + j] * 0.125f : -1e30f;
                    vv[nf*2 + j] = s;
                    m = fmaxf(m, s);
                }
            m = fmaxf(m, __shfl_xor_sync(0xFFFFFFFFu, m, 1));
            m = fmaxf(m, __shfl_xor_sync(0xFFFFFFFFu, m, 2));
            float sum = 0.0f;
            #pragma unroll
            for (int t = 0; t < 14; t++) {
                float e = (vv[t] > -1e29f) ? __expf(vv[t] - m) : 0.0f;
                vv[t] = e; sum += e;
            }
            sum += __shfl_xor_sync(0xFFFFFFFFu, sum, 1);
            sum += __shfl_xor_sync(0xFFFFFFFFu, sum, 2);
            float inv = 1.0f / sum;
            char* prow = sm + SM_QP + (sA * 4 + hA) * 9216 + lr * 144;
            #pragma unroll
            for (int nf = 0; nf < 7; nf++) {
                uint32_t pk = (lr < NTOK) ? bfx2(vv[nf*2] * inv, vv[nf*2+1] * inv) : 0u;
                *(uint32_t*)(prow + (nf * 8 + c0) * 2) = pk;
            }
            *(uint32_t*)(prow + (56 + c0) * 2) = 0u;
        }

    // ---- V GEMM (reads X); epilogue -> VT (SM_KV) + g_R.
    //      lr >= NTOK rows: bf16 ZEROS into VT ----
    mma_gemm(aG, W4 + 2 * W_MAT_U4 + wfoff, acc);
    #pragma unroll
    for (int mf = 0; mf < 4; mf++)
        #pragma unroll
        for (int rr = 0; rr < 2; rr++) {
            int lr = mf * 16 + r0 + rr * 8;      // sample = mh
            if (lr < NTOK) {
                const float* xs = xb + mh * SMP + lr * 256;
                float2 xv[4];
                #pragma unroll
                for (int nf = 0; nf < 4; nf++)
                    xv[nf] = __ldg((const float2*)(xs + nq * 32 + nf * 8 + c0));
                #pragma unroll
                for (int nf = 0; nf < 4; nf++) {
                    int c = nq * 32 + nf * 8 + c0;
                    float v0 = (acc[mf][nf][rr*2]   + sBias[512+c])   * 0.1f + xv[nf].x * 0.95f;
                    float v1 = (acc[mf][nf][rr*2+1] + sBias[512+c+1]) * 0.1f + xv[nf].y * 0.95f;
                    *(float2*)(Rb + mh * SMP + lr * 256 + c) = make_float2(v0, v1);
                    *(__nv_bfloat16*)(sm + SM_KV + mh * 36864 + c * 144 + lr * 2)       = __float2bfloat16(v0);
                    *(__nv_bfloat16*)(sm + SM_KV + mh * 36864 + (c + 1) * 144 + lr * 2) = __float2bfloat16(v1);
                }
            } else {
                const __nv_bfloat16 z = __float2bfloat16(0.0f);
                #pragma unroll
                for (int nf = 0; nf < 4; nf++) {
                    int c = nq * 32 + nf * 8 + c0;
                    *(__nv_bfloat16*)(sm + SM_KV + mh * 36864 + c * 144 + lr * 2)       = z;
                    *(__nv_bfloat16*)(sm + SM_KV + mh * 36864 + (c + 1) * 144 + lr * 2) = z;
                }
            }
        }
    __syncthreads();   // P + VT complete

    // ---- PV MMAs: warp (sA, hA, mfsA): m32 rows x n64 head cols ----
    {
        float pa[2][8][4];
        #pragma unroll
        for (int mf = 0; mf < 2; mf++)
            #pragma unroll
            for (int nf = 0; nf < 8; nf++)
                #pragma unroll
                for (int q = 0; q < 4; q++) pa[mf][nf][q] = 0.0f;

        uint32_t pbase = sb + SM_QP + (uint32_t)((sA * 4 + hA) * 9216 + mfsA * 32 * 144) + aoffP;
        uint32_t vtb = sb + SM_KV + (uint32_t)(sA * 36864)
                     + (uint32_t)((hA * 64 + (lane & 7)) * 144)
                     + (uint32_t)(((lane >> 3) & 1) * 16);
        #pragma unroll
        for (int ks = 0; ks < 4; ks++) {
            uint32_t a[2][4];
            ldsm4(a[0], pbase + ks * 32);
            ldsm4(a[1], pbase + 16 * 144 + ks * 32);
            #pragma unroll
            for (int nf = 0; nf < 8; nf++) {
                uint32_t b[2];
                ldsm2(b, vtb + (uint32_t)(nf * 8 * 144) + ks * 32);
                mma16816(pa[0][nf], a[0], b);
                mma16816(pa[1][nf], a[1], b);
            }
        }
        __syncthreads();   // ALL P/VT reads done; SM_QP/SM_KV free for fp32 x2

        // ---- PV epilogue: x2 = PV*0.1 + V'*0.95 -> fp32 smem + bf16 SM_X ----
        #pragma unroll
        for (int mf = 0; mf < 2; mf++)
            #pragma unroll
            for (int rr = 0; rr < 2; rr++) {
                int lr = mfsA * 32 + mf * 16 + rr * 8 + r0;
                int rG = sA * 64 + lr;
                if (lr < NTOK) {
                    float2 rv[8];
                    #pragma unroll
                    for (int nf = 0; nf < 8; nf++)
                        rv[nf] = *(const float2*)(Rb + sA * SMP + lr * 256 + hA * 64 + nf * 8 + c0);
                    #pragma unroll
                    for (int nf = 0; nf < 8; nf++) {
                        int c = hA * 64 + nf * 8 + c0;
                        float a0 = pa[mf][nf][rr*2]   * 0.1f + rv[nf].x * 0.95f;
                        float a1 = pa[mf][nf][rr*2+1] * 0.1f + rv[nf].y * 0.95f;
                        *(float2*)(sm + SM_F32 + rG * F32ST + c * 4) = make_float2(a0, a1);
                        *(uint32_t*)(sm + SM_X + rG * 528 + c * 2) = bfx2(a0, a1);
                    }
                } else {
                    #pragma unroll
                    for (int nf = 0; nf < 8; nf++) {
                        int c = hA * 64 + nf * 8 + c0;
                        *(uint32_t*)(sm + SM_X + rG * 528 + c * 2) = 0u;
                    }
                }
            }
    }
    __syncthreads();

    // ---- FFN in (reads bf16 x2 tile) ----
    mma_gemm(aG, W4 + 3 * W_MAT_U4 + wfoff, acc);
    __syncthreads();           // x2 reads done
    #pragma unroll
    for (int mf = 0; mf < 4; mf++)
        #pragma unroll
        for (int rr = 0; rr < 2; rr++) {
            int lr = mf * 16 + r0 + rr * 8;
            int rG = mh * 64 + lr;
            if (lr < NTOK) {
                float2 rv[4];
                #pragma unroll
                for (int nf = 0; nf < 4; nf++)
                    rv[nf] = *(const float2*)(sm + SM_F32 + rG * F32ST + (nq * 32 + nf * 8 + c0) * 4);
                #pragma unroll
                for (int nf = 0; nf < 4; nf++) {
                    int c = nq * 32 + nf * 8 + c0;
                    float t2a = (acc[mf][nf][rr*2]   + sBias[768+c])   * 0.1f + rv[nf].x * 0.95f;
                    float t2b = (acc[mf][nf][rr*2+1] + sBias[768+c+1]) * 0.1f + rv[nf].y * 0.95f;
                    float t3a = (1.0f/(1.0f + __expf(-t2a)) - 0.5f) * 0.1f + t2a * 0.95f;
                    float t3b = (1.0f/(1.0f + __expf(-t2b)) - 0.5f) * 0.1f + t2b * 0.95f;
                    *(float2*)(sm + SM_F32 + rG * F32ST + c * 4) = make_float2(t3a, t3b);
                    *(uint32_t*)(sm + SM_X + rG * 528 + c * 2) = bfx2(t3a, t3b);
                }
            } else {
                #pragma unroll
                for (int nf = 0; nf < 4; nf++) {
                    int c = nq * 32 + nf * 8 + c0;
                    *(uint32_t*)(sm + SM_X + rG * 528 + c * 2) = 0u;
                }
            }
        }
    __syncthreads();

    // ---- FFN out ----
    mma_gemm(aG, W4 + 4 * W_MAT_U4 + wfoff, acc);
    #pragma unroll
    for (int mf = 0; mf < 4; mf++)
        #pragma unroll
        for (int rr = 0; rr < 2; rr++) {
            int lr = mf * 16 + r0 + rr * 8;
            int rG = mh * 64 + lr;
            if (lr < NTOK) {
                float2 rv[4];
                #pragma unroll
                for (int nf = 0; nf < 4; nf++)
                    rv[nf] = *(const float2*)(sm + SM_F32 + rG * F32ST + (nq * 32 + nf * 8 + c0) * 4);
                #pragma unroll
                for (int nf = 0; nf < 4; nf++) {
                    int c = nq * 32 + nf * 8 + c0;
                    float o0 = (acc[mf][nf][rr*2]   + sBias[1024+c])   * 0.1f + rv[nf].x * 0.95f;
                    float o1 = (acc[mf][nf][rr*2+1] + sBias[1024+c+1]) * 0.1f + rv[nf].y * 0.95f;
                    *(float2*)(ob + mh * SMP + lr * 256 + c) = make_float2(o0, o1);
                }
            }
        }
}

// ---------------------------------------------------------------------------
extern "C" void kernel_launch(void* const* d_in, const int* in_sizes, int n_in,
                              void* d_out, int out_size)
{
    std_kernel<<<5 * DIM + 5, 256>>>(
        (const float*)d_in[1], (const float*)d_in[2],
        (const float*)d_in[3], (const float*)d_in[4],
        (const float*)d_in[5], (const float*)d_in[6],
        (const float*)d_in[7], (const float*)d_in[8],
        (const float*)d_in[9], (const float*)d_in[10]);

    cudaFuncSetAttribute(irmb_kernel,
                         cudaFuncAttributeMaxDynamicSharedMemorySize, SMEM_TOTAL);
    irmb_kernel<<<NB / 2, NT, SMEM_TOTAL>>>((const float*)d_in[0], (float*)d_out);
}

// round 15
// speedup vs baseline: 1.3277x; 1.0286x over previous
#include <cuda_runtime.h>
#include <cuda_bf16.h>
#include <math.h>
#include <stdint.h>

#define DIM  256
#define NH   4
#define HC   64
#define NTOK 49
#define NB   4096
#define SMP  12544   // NTOK*DIM

// Standardized weights in ks-paired mma-FRAGMENT order (uint4 granularity):
// uint4 index = (nblk*8 + kp)*32 + lane (per matrix), matrices contiguous.
__device__ __align__(16) __nv_bfloat16 g_Wbf[5][DIM * DIM];
__device__ float g_b[5][DIM];
// fp32 V' residual scratch per sample (only surviving gmem residual stream)
__device__ float g_R[NB][SMP];

#define W_MAT_U4 8192   // uint4 per 256x256 bf16 matrix

// ---------------------------------------------------------------------------
// Prologue: weight standardization -> ks-paired fragment-ordered bf16
// ---------------------------------------------------------------------------
__global__ __launch_bounds__(256) void std_kernel(
    const float* __restrict__ qw, const float* __restrict__ qb,
    const float* __restrict__ kw, const float* __restrict__ kb,
    const float* __restrict__ vw, const float* __restrict__ vb,
    const float* __restrict__ fiw, const float* __restrict__ fib,
    const float* __restrict__ fow, const float* __restrict__ fob)
{
    const float* wptr[5] = {qw, kw, vw, fiw, fow};
    const float* bptr[5] = {qb, kb, vb, fib, fob};
    __shared__ float s_sum[8], s_sq[8];
    int bx = blockIdx.x, t = threadIdx.x;

    float val;
    if (bx < 5 * DIM) val = wptr[bx >> 8][(bx & 255) * DIM + t];
    else              val = bptr[bx - 5 * DIM][t];

    float s = val, q = val * val;
    #pragma unroll
    for (int o = 16; o > 0; o >>= 1) {
        s += __shfl_xor_sync(0xFFFFFFFFu, s, o);
        q += __shfl_xor_sync(0xFFFFFFFFu, q, o);
    }
    if ((t & 31) == 0) { s_sum[t >> 5] = s; s_sq[t >> 5] = q; }
    __syncthreads();
    int h = t >> 6;
    float sum = s_sum[2*h] + s_sum[2*h+1];
    float sq  = s_sq [2*h] + s_sq [2*h+1];
    float mean = sum * (1.0f/64.0f);
    float var  = fmaxf(sq * (1.0f/64.0f) - mean*mean, 0.0f);
    float r    = (val - mean) / (sqrtf(var) * 16.0f);

    if (bx < 5 * DIM) {
        int m = bx >> 8, k = bx & 255, c = t;
        int kp   = k >> 5;
        int kodd = (k >> 4) & 1;
        int half = (k >> 3) & 1;
        int pos2 = (k >> 1) & 3;
        int par  = k & 1;
        int lane = (c & 7) * 4 + pos2;
        int nblk = c >> 3;
        size_t idx = ((size_t)(((nblk * 8 + kp) * 32 + lane)) << 3)
                   + (size_t)(kodd * 4 + half * 2 + par);
        ((__nv_bfloat16*)g_Wbf)[(size_t)m * DIM * DIM + idx] = __float2bfloat16(r);
    } else {
        g_b[bx - 5 * DIM][t] = r;
    }
}

// ---------------------------------------------------------------------------
// PTX helpers
// ---------------------------------------------------------------------------
__device__ __forceinline__ uint32_t s2u(const void* p) {
    uint32_t a;
    asm("{ .reg .u64 t; cvta.to.shared.u64 t, %1; cvt.u32.u64 %0, t; }" : "=r"(a) : "l"(p));
    return a;
}
__device__ __forceinline__ void ldsm4(uint32_t* r, uint32_t a) {
    asm volatile("ldmatrix.sync.aligned.m8n8.x4.shared.b16 {%0,%1,%2,%3}, [%4];"
                 : "=r"(r[0]), "=r"(r[1]), "=r"(r[2]), "=r"(r[3]) : "r"(a));
}
__device__ __forceinline__ void ldsm2(uint32_t* r, uint32_t a) {
    asm volatile("ldmatrix.sync.aligned.m8n8.x2.shared.b16 {%0,%1}, [%2];"
                 : "=r"(r[0]), "=r"(r[1]) : "r"(a));
}
__device__ __forceinline__ void mma16816(float* d, const uint32_t* a, const uint32_t* b) {
    asm volatile("mma.sync.aligned.m16n8k16.row.col.f32.bf16.bf16.f32 "
                 "{%0,%1,%2,%3}, {%4,%5,%6,%7}, {%8,%9}, {%0,%1,%2,%3};"
                 : "+f"(d[0]), "+f"(d[1]), "+f"(d[2]), "+f"(d[3])
                 : "r"(a[0]), "r"(a[1]), "r"(a[2]), "r"(a[3]), "r"(b[0]), "r"(b[1]));
}
__device__ __forceinline__ uint32_t bfx2(float lo, float hi) {   // low half = lo
    uint32_t r;
    asm("cvt.rn.bf16x2.f32 %0, %1, %2;" : "=r"(r) : "f"(hi), "f"(lo));
    return r;
}
// group barrier: 256 threads (one sample pipeline)
__device__ __forceinline__ void gbar(int id) {
    asm volatile("bar.sync %0, %1;" :: "r"(id), "r"(256) : "memory");
}

// ---------------------------------------------------------------------------
// smem regions (bytes). 2 samples per CTA, PER-SAMPLE sub-regions (36864 each)
// so the two 8-warp sample pipelines share NO bytes after the prologue:
//  SM_X  : x tile 128 x 264 bf16 (stride 528) -> x2 -> t3 (rows s*64..)
//  SM_QP + s*36864 : Q tile (64 rows x 528B) -> P tiles 4 x (64x72, stride 144)
//                    -> F32 rows 0..31 (stride 1040)
//  SM_KV + s*36864 : K tile (rows<56 x 528B) -> VT (256 ch x 72 bf16)
//                    -> F32 rows 32..63
// ---------------------------------------------------------------------------
#define SM_X    0        // 67584
#define SM_QP   67584    // 73728
#define SM_KV   141312   // 73728
#define SM_BIAS 215040   // 5120
#define SMEM_TOTAL 220160
#define F32ST   1040

#define NT 512   // 16 warps

// m128 x n256 x k256 GEMM, 16 warps: warp (mh = w>>3, nq = w&7) -> m64 x n32.
// A-fragment ping-pong; B double-buffered at kp granularity.
__device__ __forceinline__ void mma_gemm(uint32_t aBase, const uint4* __restrict__ Wf,
                                         float acc[4][4][4])
{
    #pragma unroll
    for (int mf = 0; mf < 4; mf++)
        #pragma unroll
        for (int nf = 0; nf < 4; nf++)
            #pragma unroll
            for (int q = 0; q < 4; q++) acc[mf][nf][q] = 0.0f;

    uint4 breg[2][4];
    #pragma unroll
    for (int nf = 0; nf < 4; nf++) breg[0][nf] = __ldg(Wf + nf * 256);

    uint32_t a[2][4][4];
    #pragma unroll
    for (int mf = 0; mf < 4; mf++)
        ldsm4(a[0][mf], aBase + (uint32_t)(mf * 16 * 528));

    #pragma unroll
    for (int ks = 0; ks < 16; ks++) {
        const int kp  = ks >> 1, sub = ks & 1;
        const int cur = ks & 1;
        if (sub == 0 && kp < 7) {
            #pragma unroll
            for (int nf = 0; nf < 4; nf++)
                breg[(kp + 1) & 1][nf] = __ldg(Wf + nf * 256 + (kp + 1) * 32);
        }
        if (ks < 15) {
            #pragma unroll
            for (int mf = 0; mf < 4; mf++)
                ldsm4(a[cur ^ 1][mf], aBase + (uint32_t)(mf * 16 * 528 + (ks + 1) * 32));
        }
        #pragma unroll
        for (int nf = 0; nf < 4; nf++) {
            uint32_t b[2];
            b[0] = sub ? breg[kp & 1][nf].z : breg[kp & 1][nf].x;
            b[1] = sub ? breg[kp & 1][nf].w : breg[kp & 1][nf].y;
            #pragma unroll
            for (int mf = 0; mf < 4; mf++) mma16816(acc[mf][nf], a[cur][mf], b);
        }
    }
}

__global__ __launch_bounds__(NT, 1) void irmb_kernel(
    const float* __restrict__ x, float* __restrict__ out)
{
    extern __shared__ char sm[];
    const uint32_t sb = s2u(sm);
    const int tid = threadIdx.x, w = tid >> 5, lane = tid & 31;
    const int s0 = blockIdx.x * 2;

    float* sBias = (float*)(sm + SM_BIAS);
    const float* xb = x + (size_t)s0 * SMP;
    float* ob = out + (size_t)s0 * SMP;
    float* Rb = g_R[s0];

    // prologue (cooperative across both groups): zero X, load biases, load x
    {
        uint32_t* z = (uint32_t*)(sm + SM_X);
        for (int i = tid; i < 16896; i += NT) z[i] = 0;
        const float* gb = (const float*)g_b;
        for (int i = tid; i < 1280; i += NT) sBias[i] = gb[i];
    }
    __syncthreads();
    for (int i = tid; i < 2 * SMP; i += NT) {
        int s = i / SMP, j = i - s * SMP;
        int lr = j >> 8, c = j & 255;
        *(__nv_bfloat16*)(sm + SM_X + (s * 64 + lr) * 528 + c * 2) =
            __float2bfloat16(xb[i]);
    }
    __syncthreads();   // last full-CTA barrier; groups decouple from here

    // lane constants
    const int gq = lane >> 3, iq = lane & 7;
    const uint32_t aoff  = (uint32_t)((iq + (gq & 1) * 8) * 528 + ((gq >> 1) * 8) * 2);
    const uint32_t aoffP = (uint32_t)((iq + (gq & 1) * 8) * 144 + ((gq >> 1) * 8) * 2);
    const int r0 = lane >> 2, c0 = 2 * (lane & 3);
    const int mh = w >> 3, nq = w & 7;        // sample group = mh
    const int bid = 1 + mh;                   // named barrier id per group
    const uint32_t aG = sb + SM_X + (uint32_t)(mh * 64 * 528) + aoff;
    const uint4* W4 = (const uint4*)g_Wbf;
    const int wfoff = nq * 1024 + lane;
    const int sA = w >> 3, hA = (w >> 1) & 3, mfsA = w & 1;
    // per-sample tile bases
    const int qBase = SM_QP + mh * 36864;     // Q tile (local rows 0..63)
    const int kBase = SM_KV + mh * 36864;     // K tile / VT
    // F32 residual: rows 0-31 in own P region, rows 32-63 in own VT region
    #define F32ADDR(smp, lr, c) (((lr) < 32) \
        ? (SM_QP + (smp) * 36864 + (lr) * F32ST + (c) * 4) \
        : (SM_KV + (smp) * 36864 + ((lr) - 32) * F32ST + (c) * 4))

    float acc[4][4][4];

    // ---- Q -> per-sample Q tile ----
    mma_gemm(aG, W4 + wfoff, acc);
    #pragma unroll
    for (int mf = 0; mf < 4; mf++)
        #pragma unroll
        for (int nf = 0; nf < 4; nf++)
            #pragma unroll
            for (int rr = 0; rr < 2; rr++) {
                int lr = mf * 16 + r0 + rr * 8;
                int c = nq * 32 + nf * 8 + c0;
                *(uint32_t*)(sm + qBase + lr * 528 + c * 2) =
                    bfx2(acc[mf][nf][rr*2] + sBias[c], acc[mf][nf][rr*2+1] + sBias[c+1]);
            }

    // ---- K -> per-sample K tile (rows >= 56 never read: skip) ----
    mma_gemm(aG, W4 + W_MAT_U4 + wfoff, acc);
    #pragma unroll
    for (int mf = 0; mf < 4; mf++)
        #pragma unroll
        for (int nf = 0; nf < 4; nf++)
            #pragma unroll
            for (int rr = 0; rr < 2; rr++) {
                int lr = mf * 16 + r0 + rr * 8;
                if (lr < 56) {
                    int c = nq * 32 + nf * 8 + c0;
                    *(uint32_t*)(sm + kBase + lr * 528 + c * 2) =
                        bfx2(acc[mf][nf][rr*2] + sBias[256+c], acc[mf][nf][rr*2+1] + sBias[256+c+1]);
                }
            }
    gbar(bid);

    // ---- scores: warp (sA, hA, mfsA): m32 query rows x 56 keys ----
    float sc[2][7][4];
    {
        #pragma unroll
        for (int mf = 0; mf < 2; mf++)
            #pragma unroll
            for (int nf = 0; nf < 7; nf++)
                #pragma unroll
                for (int q = 0; q < 4; q++) sc[mf][nf][q] = 0.0f;

        uint32_t qb2 = sb + (uint32_t)(SM_QP + sA * 36864) + (uint32_t)(mfsA * 32 * 528)
                     + aoff + (uint32_t)(hA * 128);
        uint32_t kb = sb + (uint32_t)(SM_KV + sA * 36864) + (uint32_t)((lane & 7) * 528)
                    + (uint32_t)(hA * 128) + (uint32_t)(((lane >> 3) & 1) * 16);
        #pragma unroll
        for (int ks = 0; ks < 4; ks++) {
            uint32_t a[2][4];
            ldsm4(a[0], qb2 + ks * 32);
            ldsm4(a[1], qb2 + 16 * 528 + ks * 32);
            #pragma unroll
            for (int nf = 0; nf < 7; nf++) {
                uint32_t b[2];
                ldsm2(b, kb + (uint32_t)(nf * 8 * 528) + ks * 32);
                mma16816(sc[0][nf], a[0], b);
                mma16816(sc[1][nf], a[1], b);
            }
        }
    }
    gbar(bid);   // group's Q/K reads done

    // ---- softmax (regs) + P store (overwrites own Q region) ----
    #pragma unroll
    for (int mf = 0; mf < 2; mf++)
        #pragma unroll
        for (int half = 0; half < 2; half++) {
            int lr = mfsA * 32 + mf * 16 + half * 8 + r0;
            float vv[14];
            float m = -1e30f;
            #pragma unroll
            for (int nf = 0; nf < 7; nf++)
                #pragma unroll
                for (int j = 0; j < 2; j++) {
                    int kk = nf * 8 + c0 + j;
                    float s = (kk < NTOK) ? sc[mf][nf][half*2 + j] * 0.125f : -1e30f;
                    vv[nf*2 + j] = s;
                    m = fmaxf(m, s);
                }
            m = fmaxf(m, __shfl_xor_sync(0xFFFFFFFFu, m, 1));
            m = fmaxf(m, __shfl_xor_sync(0xFFFFFFFFu, m, 2));
            float sum = 0.0f;
            #pragma unroll
            for (int t = 0; t < 14; t++) {
                float e = (vv[t] > -1e29f) ? __expf(vv[t] - m) : 0.0f;
                vv[t] = e; sum += e;
            }
            sum += __shfl_xor_sync(0xFFFFFFFFu, sum, 1);
            sum += __shfl_xor_sync(0xFFFFFFFFu, sum, 2);
            float inv = 1.0f / sum;
            char* prow = sm + SM_QP + sA * 36864 + hA * 9216 + lr * 144;
            #pragma unroll
            for (int nf = 0; nf < 7; nf++) {
                uint32_t pk = (lr < NTOK) ? bfx2(vv[nf*2] * inv, vv[nf*2+1] * inv) : 0u;
                *(uint32_t*)(prow + (nf * 8 + c0) * 2) = pk;
            }
            *(uint32_t*)(prow + (56 + c0) * 2) = 0u;
        }

    // ---- V GEMM (reads own X rows); epilogue -> own VT + g_R.
    //      lr >= NTOK rows: bf16 ZEROS into VT ----
    mma_gemm(aG, W4 + 2 * W_MAT_U4 + wfoff, acc);
    #pragma unroll
    for (int mf = 0; mf < 4; mf++)
        #pragma unroll
        for (int rr = 0; rr < 2; rr++) {
            int lr = mf * 16 + r0 + rr * 8;      // sample = mh
            if (lr < NTOK) {
                const float* xs = xb + mh * SMP + lr * 256;
                float2 xv[4];
                #pragma unroll
                for (int nf = 0; nf < 4; nf++)
                    xv[nf] = __ldg((const float2*)(xs + nq * 32 + nf * 8 + c0));
                #pragma unroll
                for (int nf = 0; nf < 4; nf++) {
                    int c = nq * 32 + nf * 8 + c0;
                    float v0 = (acc[mf][nf][rr*2]   + sBias[512+c])   * 0.1f + xv[nf].x * 0.95f;
                    float v1 = (acc[mf][nf][rr*2+1] + sBias[512+c+1]) * 0.1f + xv[nf].y * 0.95f;
                    *(float2*)(Rb + mh * SMP + lr * 256 + c) = make_float2(v0, v1);
                    *(__nv_bfloat16*)(sm + kBase + c * 144 + lr * 2)       = __float2bfloat16(v0);
                    *(__nv_bfloat16*)(sm + kBase + (c + 1) * 144 + lr * 2) = __float2bfloat16(v1);
                }
            } else {
                const __nv_bfloat16 z = __float2bfloat16(0.0f);
                #pragma unroll
                for (int nf = 0; nf < 4; nf++) {
                    int c = nq * 32 + nf * 8 + c0;
                    *(__nv_bfloat16*)(sm + kBase + c * 144 + lr * 2)       = z;
                    *(__nv_bfloat16*)(sm + kBase + (c + 1) * 144 + lr * 2) = z;
                }
            }
        }
    gbar(bid);   // own P + VT complete

    // ---- PV MMAs: warp (sA, hA, mfsA): m32 rows x n64 head cols ----
    {
        float pa[2][8][4];
        #pragma unroll
        for (int mf = 0; mf < 2; mf++)
            #pragma unroll
            for (int nf = 0; nf < 8; nf++)
                #pragma unroll
                for (int q = 0; q < 4; q++) pa[mf][nf][q] = 0.0f;

        uint32_t pbase = sb + (uint32_t)(SM_QP + sA * 36864 + hA * 9216 + mfsA * 32 * 144) + aoffP;
        uint32_t vtb = sb + (uint32_t)(SM_KV + sA * 36864)
                     + (uint32_t)((hA * 64 + (lane & 7)) * 144)
                     + (uint32_t)(((lane >> 3) & 1) * 16);
        #pragma unroll
        for (int ks = 0; ks < 4; ks++) {
            uint32_t a[2][4];
            ldsm4(a[0], pbase + ks * 32);
            ldsm4(a[1], pbase + 16 * 144 + ks * 32);
            #pragma unroll
            for (int nf = 0; nf < 8; nf++) {
                uint32_t b[2];
                ldsm2(b, vtb + (uint32_t)(nf * 8 * 144) + ks * 32);
                mma16816(pa[0][nf], a[0], b);
                mma16816(pa[1][nf], a[1], b);
            }
        }
        gbar(bid);   // group's P/VT reads done; own regions free for F32

        // ---- PV epilogue: x2 = PV*0.1 + V'*0.95 -> own F32 + bf16 SM_X ----
        #pragma unroll
        for (int mf = 0; mf < 2; mf++)
            #pragma unroll
            for (int rr = 0; rr < 2; rr++) {
                int lr = mfsA * 32 + mf * 16 + rr * 8 + r0;
                int rG = sA * 64 + lr;
                if (lr < NTOK) {
                    float2 rv[8];
                    #pragma unroll
                    for (int nf = 0; nf < 8; nf++)
                        rv[nf] = *(const float2*)(Rb + sA * SMP + lr * 256 + hA * 64 + nf * 8 + c0);
                    #pragma unroll
                    for (int nf = 0; nf < 8; nf++) {
                        int c = hA * 64 + nf * 8 + c0;
                        float a0 = pa[mf][nf][rr*2]   * 0.1f + rv[nf].x * 0.95f;
                        float a1 = pa[mf][nf][rr*2+1] * 0.1f + rv[nf].y * 0.95f;
                        *(float2*)(sm + F32ADDR(sA, lr, c)) = make_float2(a0, a1);
                        *(uint32_t*)(sm + SM_X + rG * 528 + c * 2) = bfx2(a0, a1);
                    }
                } else {
                    #pragma unroll
                    for (int nf = 0; nf < 8; nf++) {
                        int c = hA * 64 + nf * 8 + c0;
                        *(uint32_t*)(sm + SM_X + rG * 528 + c * 2) = 0u;
                    }
                }
            }
    }
    gbar(bid);

    // ---- FFN in (reads own bf16 x2 tile) ----
    mma_gemm(aG, W4 + 3 * W_MAT_U4 + wfoff, acc);
    gbar(bid);           // group's x2 reads done
    #pragma unroll
    for (int mf = 0; mf < 4; mf++)
        #pragma unroll
        for (int rr = 0; rr < 2; rr++) {
            int lr = mf * 16 + r0 + rr * 8;
            int rG = mh * 64 + lr;
            if (lr < NTOK) {
                float2 rv[4];
                #pragma unroll
                for (int nf = 0; nf < 4; nf++)
                    rv[nf] = *(const float2*)(sm + F32ADDR(mh, lr, nq * 32 + nf * 8 + c0));
                #pragma unroll
                for (int nf = 0; nf < 4; nf++) {
                    int c = nq * 32 + nf * 8 + c0;
                    float t2a = (acc[mf][nf][rr*2]   + sBias[768+c])   * 0.1f + rv[nf].x * 0.95f;
                    float t2b = (acc[mf][nf][rr*2+1] + sBias[768+c+1]) * 0.1f + rv[nf].y * 0.95f;
                    float t3a = (1.0f/(1.0f + __expf(-t2a)) - 0.5f) * 0.1f + t2a * 0.95f;
                    float t3b = (1.0f/(1.0f + __expf(-t2b)) - 0.5f) * 0.1f + t2b * 0.95f;
                    *(float2*)(sm + F32ADDR(mh, lr, c)) = make_float2(t3a, t3b);
                    *(uint32_t*)(sm + SM_X + rG * 528 + c * 2) = bfx2(t3a, t3b);
                }
            } else {
                #pragma unroll
                for (int nf = 0; nf < 4; nf++) {
                    int c = nq * 32 + nf * 8 + c0;
                    *(uint32_t*)(sm + SM_X + rG * 528 + c * 2) = 0u;
                }
            }
        }
    gbar(bid);

    // ---- FFN out ----
    mma_gemm(aG, W4 + 4 * W_MAT_U4 + wfoff, acc);
    #pragma unroll
    for (int mf = 0; mf < 4; mf++)
        #pragma unroll
        for (int rr = 0; rr < 2; rr++) {
            int lr = mf * 16 + r0 + rr * 8;
            if (lr < NTOK) {
                float2 rv[4];
                #pragma unroll
                for (int nf = 0; nf < 4; nf++)
                    rv[nf] = *(const float2*)(sm + F32ADDR(mh, lr, nq * 32 + nf * 8 + c0));
                #pragma unroll
                for (int nf = 0; nf < 4; nf++) {
                    int c = nq * 32 + nf * 8 + c0;
                    float o0 = (acc[mf][nf][rr*2]   + sBias[1024+c])   * 0.1f + rv[nf].x * 0.95f;
                    float o1 = (acc[mf][nf][rr*2+1] + sBias[1024+c+1]) * 0.1f + rv[nf].y * 0.95f;
                    *(float2*)(ob + mh * SMP + lr * 256 + c) = make_float2(o0, o1);
                }
            }
        }
}

// ---------------------------------------------------------------------------
extern "C" void kernel_launch(void* const* d_in, const int* in_sizes, int n_in,
                              void* d_out, int out_size)
{
    std_kernel<<<5 * DIM + 5, 256>>>(
        (const float*)d_in[1], (const float*)d_in[2],
        (const float*)d_in[3], (const float*)d_in[4],
        (const float*)d_in[5], (const float*)d_in[6],
        (const float*)d_in[7], (const float*)d_in[8],
        (const float*)d_in[9], (const float*)d_in[10]);

    cudaFuncSetAttribute(irmb_kernel,
                         cudaFuncAttributeMaxDynamicSharedMemorySize, SMEM_TOTAL);
    irmb_kernel<<<NB / 2, NT, SMEM_TOTAL>>>((const float*)d_in[0], (float*)d_out);
}

// round 16
// speedup vs baseline: 1.3721x; 1.0334x over previous
#include <cuda_runtime.h>
#include <cuda_bf16.h>
#include <math.h>
#include <stdint.h>

#define DIM  256
#define NH   4
#define HC   64
#define NTOK 49
#define NB   4096
#define SMP  12544   // NTOK*DIM

// Standardized weights in ks-paired mma-FRAGMENT order (uint4 granularity):
// uint4 index = (nblk*8 + kp)*32 + lane (per matrix), matrices contiguous.
__device__ __align__(16) __nv_bfloat16 g_Wbf[5][DIM * DIM];
__device__ float g_b[5][DIM];
// fp32 V' residual scratch per sample (only surviving gmem residual stream)
__device__ float g_R[NB][SMP];

#define W_MAT_U4 8192   // uint4 per 256x256 bf16 matrix

// ---------------------------------------------------------------------------
// Prologue: weight standardization -> ks-paired fragment-ordered bf16
// ---------------------------------------------------------------------------
__global__ __launch_bounds__(256) void std_kernel(
    const float* __restrict__ qw, const float* __restrict__ qb,
    const float* __restrict__ kw, const float* __restrict__ kb,
    const float* __restrict__ vw, const float* __restrict__ vb,
    const float* __restrict__ fiw, const float* __restrict__ fib,
    const float* __restrict__ fow, const float* __restrict__ fob)
{
    const float* wptr[5] = {qw, kw, vw, fiw, fow};
    const float* bptr[5] = {qb, kb, vb, fib, fob};
    __shared__ float s_sum[8], s_sq[8];
    int bx = blockIdx.x, t = threadIdx.x;

    float val;
    if (bx < 5 * DIM) val = wptr[bx >> 8][(bx & 255) * DIM + t];
    else              val = bptr[bx - 5 * DIM][t];

    float s = val, q = val * val;
    #pragma unroll
    for (int o = 16; o > 0; o >>= 1) {
        s += __shfl_xor_sync(0xFFFFFFFFu, s, o);
        q += __shfl_xor_sync(0xFFFFFFFFu, q, o);
    }
    if ((t & 31) == 0) { s_sum[t >> 5] = s; s_sq[t >> 5] = q; }
    __syncthreads();
    int h = t >> 6;
    float sum = s_sum[2*h] + s_sum[2*h+1];
    float sq  = s_sq [2*h] + s_sq [2*h+1];
    float mean = sum * (1.0f/64.0f);
    float var  = fmaxf(sq * (1.0f/64.0f) - mean*mean, 0.0f);
    float r    = (val - mean) / (sqrtf(var) * 16.0f);

    if (bx < 5 * DIM) {
        int m = bx >> 8, k = bx & 255, c = t;
        int kp   = k >> 5;
        int kodd = (k >> 4) & 1;
        int half = (k >> 3) & 1;
        int pos2 = (k >> 1) & 3;
        int par  = k & 1;
        int lane = (c & 7) * 4 + pos2;
        int nblk = c >> 3;
        size_t idx = ((size_t)(((nblk * 8 + kp) * 32 + lane)) << 3)
                   + (size_t)(kodd * 4 + half * 2 + par);
        ((__nv_bfloat16*)g_Wbf)[(size_t)m * DIM * DIM + idx] = __float2bfloat16(r);
    } else {
        g_b[bx - 5 * DIM][t] = r;
    }
}

// ---------------------------------------------------------------------------
// PTX helpers
// ---------------------------------------------------------------------------
__device__ __forceinline__ uint32_t s2u(const void* p) {
    uint32_t a;
    asm("{ .reg .u64 t; cvta.to.shared.u64 t, %1; cvt.u32.u64 %0, t; }" : "=r"(a) : "l"(p));
    return a;
}
__device__ __forceinline__ void ldsm4(uint32_t* r, uint32_t a) {
    asm volatile("ldmatrix.sync.aligned.m8n8.x4.shared.b16 {%0,%1,%2,%3}, [%4];"
                 : "=r"(r[0]), "=r"(r[1]), "=r"(r[2]), "=r"(r[3]) : "r"(a));
}
__device__ __forceinline__ void ldsm2(uint32_t* r, uint32_t a) {
    asm volatile("ldmatrix.sync.aligned.m8n8.x2.shared.b16 {%0,%1}, [%2];"
                 : "=r"(r[0]), "=r"(r[1]) : "r"(a));
}
__device__ __forceinline__ void mma16816(float* d, const uint32_t* a, const uint32_t* b) {
    asm volatile("mma.sync.aligned.m16n8k16.row.col.f32.bf16.bf16.f32 "
                 "{%0,%1,%2,%3}, {%4,%5,%6,%7}, {%8,%9}, {%0,%1,%2,%3};"
                 : "+f"(d[0]), "+f"(d[1]), "+f"(d[2]), "+f"(d[3])
                 : "r"(a[0]), "r"(a[1]), "r"(a[2]), "r"(a[3]), "r"(b[0]), "r"(b[1]));
}
__device__ __forceinline__ uint32_t bfx2(float lo, float hi) {   // low half = lo
    uint32_t r;
    asm("cvt.rn.bf16x2.f32 %0, %1, %2;" : "=r"(r) : "f"(hi), "f"(lo));
    return r;
}
// group barrier: 256 threads (one sample pipeline)
__device__ __forceinline__ void gbar(int id) {
    asm volatile("bar.sync %0, %1;" :: "r"(id), "r"(256) : "memory");
}

// ---------------------------------------------------------------------------
// smem regions (bytes). 2 samples per CTA, PER-SAMPLE sub-regions (36864 each):
//  SM_X  : x tile 128 x 264 bf16 (stride 528) -> x2 -> t3 (rows s*64..)
//  SM_QP + s*36864 : Q tile (64 rows x 528B) -> P tiles 4 x (64x72, stride 144)
//                    -> F32 rows 0..31 (stride 1040)
//  SM_KV + s*36864 : K tile (rows<56 x 528B) -> VT (256 ch x 72 bf16)
//                    -> F32 rows 32..63
// ---------------------------------------------------------------------------
#define SM_X    0        // 67584
#define SM_QP   67584    // 73728
#define SM_KV   141312   // 73728
#define SM_BIAS 215040   // 5120
#define SMEM_TOTAL 220160
#define F32ST   1040

#define NT 512   // 16 warps

// prefetch first k-pair of B for a GEMM
__device__ __forceinline__ void pre_b0(const uint4* __restrict__ Wf, uint4 b0[4]) {
    #pragma unroll
    for (int nf = 0; nf < 4; nf++) b0[nf] = __ldg(Wf + nf * 256);
}

// m128 x n256 x k256 GEMM, 16 warps: warp (mh = w>>3, nq = w&7) -> m64 x n32.
// A-fragment ping-pong; B double-buffered at kp granularity; b0 preloaded.
__device__ __forceinline__ void mma_gemm(uint32_t aBase, const uint4* __restrict__ Wf,
                                         float acc[4][4][4], const uint4 b0[4])
{
    #pragma unroll
    for (int mf = 0; mf < 4; mf++)
        #pragma unroll
        for (int nf = 0; nf < 4; nf++)
            #pragma unroll
            for (int q = 0; q < 4; q++) acc[mf][nf][q] = 0.0f;

    uint4 breg[2][4];
    #pragma unroll
    for (int nf = 0; nf < 4; nf++) breg[0][nf] = b0[nf];

    uint32_t a[2][4][4];
    #pragma unroll
    for (int mf = 0; mf < 4; mf++)
        ldsm4(a[0][mf], aBase + (uint32_t)(mf * 16 * 528));

    #pragma unroll
    for (int ks = 0; ks < 16; ks++) {
        const int kp  = ks >> 1, sub = ks & 1;
        const int cur = ks & 1;
        if (sub == 0 && kp < 7) {
            #pragma unroll
            for (int nf = 0; nf < 4; nf++)
                breg[(kp + 1) & 1][nf] = __ldg(Wf + nf * 256 + (kp + 1) * 32);
        }
        if (ks < 15) {
            #pragma unroll
            for (int mf = 0; mf < 4; mf++)
                ldsm4(a[cur ^ 1][mf], aBase + (uint32_t)(mf * 16 * 528 + (ks + 1) * 32));
        }
        #pragma unroll
        for (int nf = 0; nf < 4; nf++) {
            uint32_t b[2];
            b[0] = sub ? breg[kp & 1][nf].z : breg[kp & 1][nf].x;
            b[1] = sub ? breg[kp & 1][nf].w : breg[kp & 1][nf].y;
            #pragma unroll
            for (int mf = 0; mf < 4; mf++) mma16816(acc[mf][nf], a[cur][mf], b);
        }
    }
}

__global__ __launch_bounds__(NT, 1) void irmb_kernel(
    const float* __restrict__ x, float* __restrict__ out)
{
    extern __shared__ char sm[];
    const uint32_t sb = s2u(sm);
    const int tid = threadIdx.x, w = tid >> 5, lane = tid & 31;
    const int s0 = blockIdx.x * 2;

    float* sBias = (float*)(sm + SM_BIAS);
    const float* xb = x + (size_t)s0 * SMP;
    float* ob = out + (size_t)s0 * SMP;
    float* Rb = g_R[s0];

    // lane constants (needed early for prefetch)
    const int gq = lane >> 3, iq = lane & 7;
    const uint32_t aoff  = (uint32_t)((iq + (gq & 1) * 8) * 528 + ((gq >> 1) * 8) * 2);
    const uint32_t aoffP = (uint32_t)((iq + (gq & 1) * 8) * 144 + ((gq >> 1) * 8) * 2);
    const int r0 = lane >> 2, c0 = 2 * (lane & 3);
    const int mh = w >> 3, nq = w & 7;        // sample group = mh
    const int bid = 1 + mh;                   // named barrier id per group
    const uint32_t aG = sb + SM_X + (uint32_t)(mh * 64 * 528) + aoff;
    const uint4* W4 = (const uint4*)g_Wbf;
    const int wfoff = nq * 1024 + lane;
    const int sA = w >> 3, hA = (w >> 1) & 3, mfsA = w & 1;
    const int qBase = SM_QP + mh * 36864;     // Q tile (local rows 0..63)
    const int kBase = SM_KV + mh * 36864;     // K tile / VT
    #define F32ADDR(smp, lr, c) (((lr) < 32) \
        ? (SM_QP + (smp) * 36864 + (lr) * F32ST + (c) * 4) \
        : (SM_KV + (smp) * 36864 + ((lr) - 32) * F32ST + (c) * 4))

    uint4 nb[4];
    pre_b0(W4 + wfoff, nb);    // W0 B0: in flight across the whole prologue

    // prologue (cooperative): zero X, load biases, load x (vectorized)
    {
        uint32_t* z = (uint32_t*)(sm + SM_X);
        for (int i = tid; i < 16896; i += NT) z[i] = 0;
        const float* gb = (const float*)g_b;
        for (int i = tid; i < 1280; i += NT) sBias[i] = gb[i];
    }
    __syncthreads();
    for (int i = tid; i < (2 * SMP) / 4; i += NT) {
        int idx = i * 4;
        int s = idx / SMP, j = idx - s * SMP;
        int lr = j >> 8, c = j & 255;
        float4 v = __ldg((const float4*)(xb + idx));
        uint2 pk;
        pk.x = bfx2(v.x, v.y);
        pk.y = bfx2(v.z, v.w);
        *(uint2*)(sm + SM_X + (s * 64 + lr) * 528 + c * 2) = pk;
    }
    __syncthreads();   // last full-CTA barrier; groups decouple from here

    float acc[4][4][4];

    // ---- Q GEMM ----
    mma_gemm(aG, W4 + wfoff, acc, nb);
    pre_b0(W4 + W_MAT_U4 + wfoff, nb);   // K B0 in flight across Q epilogue
    #pragma unroll
    for (int mf = 0; mf < 4; mf++)
        #pragma unroll
        for (int nf = 0; nf < 4; nf++)
            #pragma unroll
            for (int rr = 0; rr < 2; rr++) {
                int lr = mf * 16 + r0 + rr * 8;
                int c = nq * 32 + nf * 8 + c0;
                *(uint32_t*)(sm + qBase + lr * 528 + c * 2) =
                    bfx2(acc[mf][nf][rr*2] + sBias[c], acc[mf][nf][rr*2+1] + sBias[c+1]);
            }

    // ---- K GEMM (rows >= 56 never read: skip stores) ----
    mma_gemm(aG, W4 + W_MAT_U4 + wfoff, acc, nb);
    #pragma unroll
    for (int mf = 0; mf < 4; mf++)
        #pragma unroll
        for (int nf = 0; nf < 4; nf++)
            #pragma unroll
            for (int rr = 0; rr < 2; rr++) {
                int lr = mf * 16 + r0 + rr * 8;
                if (lr < 56) {
                    int c = nq * 32 + nf * 8 + c0;
                    *(uint32_t*)(sm + kBase + lr * 528 + c * 2) =
                        bfx2(acc[mf][nf][rr*2] + sBias[256+c], acc[mf][nf][rr*2+1] + sBias[256+c+1]);
                }
            }
    gbar(bid);

    // ---- scores: warp (sA, hA, mfsA): m32 query rows x 56 keys ----
    float sc[2][7][4];
    {
        #pragma unroll
        for (int mf = 0; mf < 2; mf++)
            #pragma unroll
            for (int nf = 0; nf < 7; nf++)
                #pragma unroll
                for (int q = 0; q < 4; q++) sc[mf][nf][q] = 0.0f;

        uint32_t qb2 = sb + (uint32_t)(SM_QP + sA * 36864) + (uint32_t)(mfsA * 32 * 528)
                     + aoff + (uint32_t)(hA * 128);
        uint32_t kb = sb + (uint32_t)(SM_KV + sA * 36864) + (uint32_t)((lane & 7) * 528)
                    + (uint32_t)(hA * 128) + (uint32_t)(((lane >> 3) & 1) * 16);
        #pragma unroll
        for (int ks = 0; ks < 4; ks++) {
            uint32_t a[2][4];
            ldsm4(a[0], qb2 + ks * 32);
            ldsm4(a[1], qb2 + 16 * 528 + ks * 32);
            #pragma unroll
            for (int nf = 0; nf < 7; nf++) {
                uint32_t b[2];
                ldsm2(b, kb + (uint32_t)(nf * 8 * 528) + ks * 32);
                mma16816(sc[0][nf], a[0], b);
                mma16816(sc[1][nf], a[1], b);
            }
        }
    }
    gbar(bid);   // group's Q/K reads done
    pre_b0(W4 + 2 * W_MAT_U4 + wfoff, nb);   // V B0 in flight across softmax

    // ---- softmax (regs) + P store (overwrites own Q region) ----
    #pragma unroll
    for (int mf = 0; mf < 2; mf++)
        #pragma unroll
        for (int half = 0; half < 2; half++) {
            int lr = mfsA * 32 + mf * 16 + half * 8 + r0;
            float vv[14];
            float m = -1e30f;
            #pragma unroll
            for (int nf = 0; nf < 7; nf++)
                #pragma unroll
                for (int j = 0; j < 2; j++) {
                    int kk = nf * 8 + c0 + j;
                    float s = (kk < NTOK) ? sc[mf][nf][half*2 + j] * 0.125f : -1e30f;
                    vv[nf*2 + j] = s;
                    m = fmaxf(m, s);
                }
            m = fmaxf(m, __shfl_xor_sync(0xFFFFFFFFu, m, 1));
            m = fmaxf(m, __shfl_xor_sync(0xFFFFFFFFu, m, 2));
            float sum = 0.0f;
            #pragma unroll
            for (int t = 0; t < 14; t++) {
                float e = (vv[t] > -1e29f) ? __expf(vv[t] - m) : 0.0f;
                vv[t] = e; sum += e;
            }
            sum += __shfl_xor_sync(0xFFFFFFFFu, sum, 1);
            sum += __shfl_xor_sync(0xFFFFFFFFu, sum, 2);
            float inv = 1.0f / sum;
            char* prow = sm + SM_QP + sA * 36864 + hA * 9216 + lr * 144;
            #pragma unroll
            for (int nf = 0; nf < 7; nf++) {
                uint32_t pk = (lr < NTOK) ? bfx2(vv[nf*2] * inv, vv[nf*2+1] * inv) : 0u;
                *(uint32_t*)(prow + (nf * 8 + c0) * 2) = pk;
            }
            *(uint32_t*)(prow + (56 + c0) * 2) = 0u;
        }

    // ---- V GEMM; epilogue -> own VT + g_R (pad rows: bf16 zeros into VT) ----
    mma_gemm(aG, W4 + 2 * W_MAT_U4 + wfoff, acc, nb);
    #pragma unroll
    for (int mf = 0; mf < 4; mf++)
        #pragma unroll
        for (int rr = 0; rr < 2; rr++) {
            int lr = mf * 16 + r0 + rr * 8;      // sample = mh
            if (lr < NTOK) {
                const float* xs = xb + mh * SMP + lr * 256;
                float2 xv[4];
                #pragma unroll
                for (int nf = 0; nf < 4; nf++)
                    xv[nf] = __ldg((const float2*)(xs + nq * 32 + nf * 8 + c0));
                #pragma unroll
                for (int nf = 0; nf < 4; nf++) {
                    int c = nq * 32 + nf * 8 + c0;
                    float v0 = (acc[mf][nf][rr*2]   + sBias[512+c])   * 0.1f + xv[nf].x * 0.95f;
                    float v1 = (acc[mf][nf][rr*2+1] + sBias[512+c+1]) * 0.1f + xv[nf].y * 0.95f;
                    *(float2*)(Rb + mh * SMP + lr * 256 + c) = make_float2(v0, v1);
                    *(__nv_bfloat16*)(sm + kBase + c * 144 + lr * 2)       = __float2bfloat16(v0);
                    *(__nv_bfloat16*)(sm + kBase + (c + 1) * 144 + lr * 2) = __float2bfloat16(v1);
                }
            } else {
                const __nv_bfloat16 z = __float2bfloat16(0.0f);
                #pragma unroll
                for (int nf = 0; nf < 4; nf++) {
                    int c = nq * 32 + nf * 8 + c0;
                    *(__nv_bfloat16*)(sm + kBase + c * 144 + lr * 2)       = z;
                    *(__nv_bfloat16*)(sm + kBase + (c + 1) * 144 + lr * 2) = z;
                }
            }
        }
    gbar(bid);   // own P + VT complete

    // ---- PV MMAs: warp (sA, hA, mfsA): m32 rows x n64 head cols ----
    {
        float pa[2][8][4];
        #pragma unroll
        for (int mf = 0; mf < 2; mf++)
            #pragma unroll
            for (int nf = 0; nf < 8; nf++)
                #pragma unroll
                for (int q = 0; q < 4; q++) pa[mf][nf][q] = 0.0f;

        uint32_t pbase = sb + (uint32_t)(SM_QP + sA * 36864 + hA * 9216 + mfsA * 32 * 144) + aoffP;
        uint32_t vtb = sb + (uint32_t)(SM_KV + sA * 36864)
                     + (uint32_t)((hA * 64 + (lane & 7)) * 144)
                     + (uint32_t)(((lane >> 3) & 1) * 16);
        #pragma unroll
        for (int ks = 0; ks < 4; ks++) {
            uint32_t a[2][4];
            ldsm4(a[0], pbase + ks * 32);
            ldsm4(a[1], pbase + 16 * 144 + ks * 32);
            #pragma unroll
            for (int nf = 0; nf < 8; nf++) {
                uint32_t b[2];
                ldsm2(b, vtb + (uint32_t)(nf * 8 * 144) + ks * 32);
                mma16816(pa[0][nf], a[0], b);
                mma16816(pa[1][nf], a[1], b);
            }
        }
        gbar(bid);   // group's P/VT reads done; own regions free for F32
        pre_b0(W4 + 3 * W_MAT_U4 + wfoff, nb);   // FFN1 B0 across PV epilogue

        // ---- PV epilogue: x2 = PV*0.1 + V'*0.95 -> own F32 + bf16 SM_X ----
        // (X pad rows stay zero from prologue; no re-zeroing needed)
        #pragma unroll
        for (int mf = 0; mf < 2; mf++)
            #pragma unroll
            for (int rr = 0; rr < 2; rr++) {
                int lr = mfsA * 32 + mf * 16 + rr * 8 + r0;
                int rG = sA * 64 + lr;
                if (lr < NTOK) {
                    float2 rv[8];
                    #pragma unroll
                    for (int nf = 0; nf < 8; nf++)
                        rv[nf] = *(const float2*)(Rb + sA * SMP + lr * 256 + hA * 64 + nf * 8 + c0);
                    #pragma unroll
                    for (int nf = 0; nf < 8; nf++) {
                        int c = hA * 64 + nf * 8 + c0;
                        float a0 = pa[mf][nf][rr*2]   * 0.1f + rv[nf].x * 0.95f;
                        float a1 = pa[mf][nf][rr*2+1] * 0.1f + rv[nf].y * 0.95f;
                        *(float2*)(sm + F32ADDR(sA, lr, c)) = make_float2(a0, a1);
                        *(uint32_t*)(sm + SM_X + rG * 528 + c * 2) = bfx2(a0, a1);
                    }
                }
            }
    }
    gbar(bid);

    // ---- FFN in (reads own bf16 x2 tile) ----
    mma_gemm(aG, W4 + 3 * W_MAT_U4 + wfoff, acc, nb);
    pre_b0(W4 + 4 * W_MAT_U4 + wfoff, nb);   // FFN2 B0 across FFN1 epilogue
    gbar(bid);           // group's x2 reads done
    #pragma unroll
    for (int mf = 0; mf < 4; mf++)
        #pragma unroll
        for (int rr = 0; rr < 2; rr++) {
            int lr = mf * 16 + r0 + rr * 8;
            int rG = mh * 64 + lr;
            if (lr < NTOK) {
                float2 rv[4];
                #pragma unroll
                for (int nf = 0; nf < 4; nf++)
                    rv[nf] = *(const float2*)(sm + F32ADDR(mh, lr, nq * 32 + nf * 8 + c0));
                #pragma unroll
                for (int nf = 0; nf < 4; nf++) {
                    int c = nq * 32 + nf * 8 + c0;
                    float t2a = (acc[mf][nf][rr*2]   + sBias[768+c])   * 0.1f + rv[nf].x * 0.95f;
                    float t2b = (acc[mf][nf][rr*2+1] + sBias[768+c+1]) * 0.1f + rv[nf].y * 0.95f;
                    float t3a = (1.0f/(1.0f + __expf(-t2a)) - 0.5f) * 0.1f + t2a * 0.95f;
                    float t3b = (1.0f/(1.0f + __expf(-t2b)) - 0.5f) * 0.1f + t2b * 0.95f;
                    *(float2*)(sm + F32ADDR(mh, lr, c)) = make_float2(t3a, t3b);
                    *(uint32_t*)(sm + SM_X + rG * 528 + c * 2) = bfx2(t3a, t3b);
                }
            }
        }
    gbar(bid);

    // ---- FFN out ----
    mma_gemm(aG, W4 + 4 * W_MAT_U4 + wfoff, acc, nb);
    #pragma unroll
    for (int mf = 0; mf < 4; mf++)
        #pragma unroll
        for (int rr = 0; rr < 2; rr++) {
            int lr = mf * 16 + r0 + rr * 8;
            if (lr < NTOK) {
                float2 rv[4];
                #pragma unroll
                for (int nf = 0; nf < 4; nf++)
                    rv[nf] = *(const float2*)(sm + F32ADDR(mh, lr, nq * 32 + nf * 8 + c0));
                #pragma unroll
                for (int nf = 0; nf < 4; nf++) {
                    int c = nq * 32 + nf * 8 + c0;
                    float o0 = (acc[mf][nf][rr*2]   + sBias[1024+c])   * 0.1f + rv[nf].x * 0.95f;
                    float o1 = (acc[mf][nf][rr*2+1] + sBias[1024+c+1]) * 0.1f + rv[nf].y * 0.95f;
                    *(float2*)(ob + mh * SMP + lr * 256 + c) = make_float2(o0, o1);
                }
            }
        }
}

// ---------------------------------------------------------------------------
extern "C" void kernel_launch(void* const* d_in, const int* in_sizes, int n_in,
                              void* d_out, int out_size)
{
    std_kernel<<<5 * DIM + 5, 256>>>(
        (const float*)d_in[1], (const float*)d_in[2],
        (const float*)d_in[3], (const float*)d_in[4],
        (const float*)d_in[5], (const float*)d_in[6],
        (const float*)d_in[7], (const float*)d_in[8],
        (const float*)d_in[9], (const float*)d_in[10]);

    cudaFuncSetAttribute(irmb_kernel,
                         cudaFuncAttributeMaxDynamicSharedMemorySize, SMEM_TOTAL);
    irmb_kernel<<<NB / 2, NT, SMEM_TOTAL>>>((const float*)d_in[0], (float*)d_out);
}

// round 17
// speedup vs baseline: 1.4939x; 1.0888x over previous
#include <cuda_runtime.h>
#include <cuda_bf16.h>
#include <math.h>
#include <stdint.h>

#define DIM  256
#define NH   4
#define HC   64
#define NTOK 49
#define NB   4096
#define SMP  12544   // NTOK*DIM

// Standardized weights in ks-paired mma-FRAGMENT order (uint4 granularity):
// uint4 index = (nblk*8 + kp)*32 + lane (per matrix), matrices contiguous.
__device__ __align__(16) __nv_bfloat16 g_Wbf[5][DIM * DIM];
__device__ float g_b[5][DIM];
// fp32 V' residual scratch per sample (only surviving gmem residual stream)
__device__ float g_R[NB][SMP];

#define W_MAT_U4 8192   // uint4 per 256x256 bf16 matrix
#define GRID 148        // <= SM count on all sm_103a parts; 1 CTA/SM, single wave

// ---------------------------------------------------------------------------
// Prologue: weight standardization -> ks-paired fragment-ordered bf16
// ---------------------------------------------------------------------------
__global__ __launch_bounds__(256) void std_kernel(
    const float* __restrict__ qw, const float* __restrict__ qb,
    const float* __restrict__ kw, const float* __restrict__ kb,
    const float* __restrict__ vw, const float* __restrict__ vb,
    const float* __restrict__ fiw, const float* __restrict__ fib,
    const float* __restrict__ fow, const float* __restrict__ fob)
{
    const float* wptr[5] = {qw, kw, vw, fiw, fow};
    const float* bptr[5] = {qb, kb, vb, fib, fob};
    __shared__ float s_sum[8], s_sq[8];
    int bx = blockIdx.x, t = threadIdx.x;

    float val;
    if (bx < 5 * DIM) val = wptr[bx >> 8][(bx & 255) * DIM + t];
    else              val = bptr[bx - 5 * DIM][t];

    float s = val, q = val * val;
    #pragma unroll
    for (int o = 16; o > 0; o >>= 1) {
        s += __shfl_xor_sync(0xFFFFFFFFu, s, o);
        q += __shfl_xor_sync(0xFFFFFFFFu, q, o);
    }
    if ((t & 31) == 0) { s_sum[t >> 5] = s; s_sq[t >> 5] = q; }
    __syncthreads();
    int h = t >> 6;
    float sum = s_sum[2*h] + s_sum[2*h+1];
    float sq  = s_sq [2*h] + s_sq [2*h+1];
    float mean = sum * (1.0f/64.0f);
    float var  = fmaxf(sq * (1.0f/64.0f) - mean*mean, 0.0f);
    float r    = (val - mean) / (sqrtf(var) * 16.0f);

    if (bx < 5 * DIM) {
        int m = bx >> 8, k = bx & 255, c = t;
        int kp   = k >> 5;
        int kodd = (k >> 4) & 1;
        int half = (k >> 3) & 1;
        int pos2 = (k >> 1) & 3;
        int par  = k & 1;
        int lane = (c & 7) * 4 + pos2;
        int nblk = c >> 3;
        size_t idx = ((size_t)(((nblk * 8 + kp) * 32 + lane)) << 3)
                   + (size_t)(kodd * 4 + half * 2 + par);
        ((__nv_bfloat16*)g_Wbf)[(size_t)m * DIM * DIM + idx] = __float2bfloat16(r);
    } else {
        g_b[bx - 5 * DIM][t] = r;
    }
}

// ---------------------------------------------------------------------------
// PTX helpers
// ---------------------------------------------------------------------------
__device__ __forceinline__ uint32_t s2u(const void* p) {
    uint32_t a;
    asm("{ .reg .u64 t; cvta.to.shared.u64 t, %1; cvt.u32.u64 %0, t; }" : "=r"(a) : "l"(p));
    return a;
}
__device__ __forceinline__ void ldsm4(uint32_t* r, uint32_t a) {
    asm volatile("ldmatrix.sync.aligned.m8n8.x4.shared.b16 {%0,%1,%2,%3}, [%4];"
                 : "=r"(r[0]), "=r"(r[1]), "=r"(r[2]), "=r"(r[3]) : "r"(a));
}
__device__ __forceinline__ void ldsm2(uint32_t* r, uint32_t a) {
    asm volatile("ldmatrix.sync.aligned.m8n8.x2.shared.b16 {%0,%1}, [%2];"
                 : "=r"(r[0]), "=r"(r[1]) : "r"(a));
}
__device__ __forceinline__ void mma16816(float* d, const uint32_t* a, const uint32_t* b) {
    asm volatile("mma.sync.aligned.m16n8k16.row.col.f32.bf16.bf16.f32 "
                 "{%0,%1,%2,%3}, {%4,%5,%6,%7}, {%8,%9}, {%0,%1,%2,%3};"
                 : "+f"(d[0]), "+f"(d[1]), "+f"(d[2]), "+f"(d[3])
                 : "r"(a[0]), "r"(a[1]), "r"(a[2]), "r"(a[3]), "r"(b[0]), "r"(b[1]));
}
__device__ __forceinline__ uint32_t bfx2(float lo, float hi) {   // low half = lo
    uint32_t r;
    asm("cvt.rn.bf16x2.f32 %0, %1, %2;" : "=r"(r) : "f"(hi), "f"(lo));
    return r;
}
// group barrier: 256 threads (one sample pipeline)
__device__ __forceinline__ void gbar(int id) {
    asm volatile("bar.sync %0, %1;" :: "r"(id), "r"(256) : "memory");
}

// ---------------------------------------------------------------------------
// smem regions (bytes). 2 independent sample pipelines per CTA:
//  SM_X  : x tile 128 x 264 bf16 (stride 528) -> x2 -> t3 (rows mh*64..)
//  SM_QP + s*36864 : Q tile (64 rows x 528B) -> P tiles 4 x (64x72, stride 144)
//                    -> F32 rows 0..31 (stride 1040)
//  SM_KV + s*36864 : K tile (rows<56 x 528B) -> VT (256 ch x 72 bf16)
//                    -> F32 rows 32..63
// ---------------------------------------------------------------------------
#define SM_X    0        // 67584
#define SM_QP   67584    // 73728
#define SM_KV   141312   // 73728
#define SM_BIAS 215040   // 5120
#define SMEM_TOTAL 220160
#define F32ST   1040

#define NT 512   // 16 warps

// prefetch first k-pair of B for a GEMM
__device__ __forceinline__ void pre_b0(const uint4* __restrict__ Wf, uint4 b0[4]) {
    #pragma unroll
    for (int nf = 0; nf < 4; nf++) b0[nf] = __ldg(Wf + nf * 256);
}

// m64 x n256 x k256 per-group GEMM: warp nq -> m64 x n32.
// A-fragment ping-pong; B double-buffered at kp granularity; b0 preloaded.
__device__ __forceinline__ void mma_gemm(uint32_t aBase, const uint4* __restrict__ Wf,
                                         float acc[4][4][4], const uint4 b0[4])
{
    #pragma unroll
    for (int mf = 0; mf < 4; mf++)
        #pragma unroll
        for (int nf = 0; nf < 4; nf++)
            #pragma unroll
            for (int q = 0; q < 4; q++) acc[mf][nf][q] = 0.0f;

    uint4 breg[2][4];
    #pragma unroll
    for (int nf = 0; nf < 4; nf++) breg[0][nf] = b0[nf];

    uint32_t a[2][4][4];
    #pragma unroll
    for (int mf = 0; mf < 4; mf++)
        ldsm4(a[0][mf], aBase + (uint32_t)(mf * 16 * 528));

    #pragma unroll
    for (int ks = 0; ks < 16; ks++) {
        const int kp  = ks >> 1, sub = ks & 1;
        const int cur = ks & 1;
        if (sub == 0 && kp < 7) {
            #pragma unroll
            for (int nf = 0; nf < 4; nf++)
                breg[(kp + 1) & 1][nf] = __ldg(Wf + nf * 256 + (kp + 1) * 32);
        }
        if (ks < 15) {
            #pragma unroll
            for (int mf = 0; mf < 4; mf++)
                ldsm4(a[cur ^ 1][mf], aBase + (uint32_t)(mf * 16 * 528 + (ks + 1) * 32));
        }
        #pragma unroll
        for (int nf = 0; nf < 4; nf++) {
            uint32_t b[2];
            b[0] = sub ? breg[kp & 1][nf].z : breg[kp & 1][nf].x;
            b[1] = sub ? breg[kp & 1][nf].w : breg[kp & 1][nf].y;
            #pragma unroll
            for (int mf = 0; mf < 4; mf++) mma16816(acc[mf][nf], a[cur][mf], b);
        }
    }
}

__global__ __launch_bounds__(NT, 1) void irmb_kernel(
    const float* __restrict__ x, float* __restrict__ out)
{
    extern __shared__ char sm[];
    const uint32_t sb = s2u(sm);
    const int tid = threadIdx.x, w = tid >> 5, lane = tid & 31;
    const int wg_tid = tid & 255;

    float* sBias = (float*)(sm + SM_BIAS);

    // lane constants
    const int gq = lane >> 3, iq = lane & 7;
    const uint32_t aoff  = (uint32_t)((iq + (gq & 1) * 8) * 528 + ((gq >> 1) * 8) * 2);
    const uint32_t aoffP = (uint32_t)((iq + (gq & 1) * 8) * 144 + ((gq >> 1) * 8) * 2);
    const int r0 = lane >> 2, c0 = 2 * (lane & 3);
    const int mh = w >> 3, nq = w & 7;        // sample group = mh
    const int bid = 1 + mh;                   // named barrier id per group
    const uint32_t aG = sb + SM_X + (uint32_t)(mh * 64 * 528) + aoff;
    const uint4* W4 = (const uint4*)g_Wbf;
    const int wfoff = nq * 1024 + lane;
    const int hA = (w >> 1) & 3, mfsA = w & 1;
    const int qBase = SM_QP + mh * 36864;     // Q tile (local rows 0..63)
    const int kBase = SM_KV + mh * 36864;     // K tile / VT
    #define F32ADDR(smp, lr, c) (((lr) < 32) \
        ? (SM_QP + (smp) * 36864 + (lr) * F32ST + (c) * 4) \
        : (SM_KV + (smp) * 36864 + ((lr) - 32) * F32ST + (c) * 4))

    // one-time init: zero X tile (incl. all pads), load biases
    {
        uint32_t* z = (uint32_t*)(sm + SM_X);
        for (int i = tid; i < 16896; i += NT) z[i] = 0;
        const float* gb = (const float*)g_b;
        for (int i = tid; i < 1280; i += NT) sBias[i] = gb[i];
    }
    __syncthreads();   // only full-CTA barrier; groups independent from here

    uint4 nb[4];
    float acc[4][4][4];

    // persistent loop: each group owns its own sample stream
    for (int s = blockIdx.x * 2 + mh; s < NB; s += 2 * GRID) {
        const float* xb = x + (size_t)s * SMP;
        float* ob = out + (size_t)s * SMP;
        float* Rb = g_R[s];

        pre_b0(W4 + wfoff, nb);   // Q B0 in flight across x load
        gbar(bid);   // prior iteration's X reads (FFN2 mainloop) complete

        // group-local x load -> own X rows (vectorized)
        for (int i = wg_tid; i < SMP / 4; i += 256) {
            int idx = i * 4;
            int lr = idx >> 8, c = idx & 255;
            float4 v = __ldg((const float4*)(xb + idx));
            uint2 pk;
            pk.x = bfx2(v.x, v.y);
            pk.y = bfx2(v.z, v.w);
            *(uint2*)(sm + SM_X + (mh * 64 + lr) * 528 + c * 2) = pk;
        }
        gbar(bid);

        // ---- Q GEMM ----
        mma_gemm(aG, W4 + wfoff, acc, nb);
        pre_b0(W4 + W_MAT_U4 + wfoff, nb);   // K B0 across Q epilogue
        #pragma unroll
        for (int mf = 0; mf < 4; mf++)
            #pragma unroll
            for (int nf = 0; nf < 4; nf++)
                #pragma unroll
                for (int rr = 0; rr < 2; rr++) {
                    int lr = mf * 16 + r0 + rr * 8;
                    int c = nq * 32 + nf * 8 + c0;
                    *(uint32_t*)(sm + qBase + lr * 528 + c * 2) =
                        bfx2(acc[mf][nf][rr*2] + sBias[c], acc[mf][nf][rr*2+1] + sBias[c+1]);
                }

        // ---- K GEMM (rows >= 56 never read: skip stores) ----
        mma_gemm(aG, W4 + W_MAT_U4 + wfoff, acc, nb);
        #pragma unroll
        for (int mf = 0; mf < 4; mf++)
            #pragma unroll
            for (int nf = 0; nf < 4; nf++)
                #pragma unroll
                for (int rr = 0; rr < 2; rr++) {
                    int lr = mf * 16 + r0 + rr * 8;
                    if (lr < 56) {
                        int c = nq * 32 + nf * 8 + c0;
                        *(uint32_t*)(sm + kBase + lr * 528 + c * 2) =
                            bfx2(acc[mf][nf][rr*2] + sBias[256+c], acc[mf][nf][rr*2+1] + sBias[256+c+1]);
                    }
                }
        gbar(bid);

        // ---- scores: warp (hA, mfsA): m32 query rows x 56 keys ----
        float sc[2][7][4];
        {
            #pragma unroll
            for (int mf = 0; mf < 2; mf++)
                #pragma unroll
                for (int nf = 0; nf < 7; nf++)
                    #pragma unroll
                    for (int q = 0; q < 4; q++) sc[mf][nf][q] = 0.0f;

            uint32_t qb2 = sb + (uint32_t)qBase + (uint32_t)(mfsA * 32 * 528)
                         + aoff + (uint32_t)(hA * 128);
            uint32_t kb = sb + (uint32_t)kBase + (uint32_t)((lane & 7) * 528)
                        + (uint32_t)(hA * 128) + (uint32_t)(((lane >> 3) & 1) * 16);
            #pragma unroll
            for (int ks = 0; ks < 4; ks++) {
                uint32_t a[2][4];
                ldsm4(a[0], qb2 + ks * 32);
                ldsm4(a[1], qb2 + 16 * 528 + ks * 32);
                #pragma unroll
                for (int nf = 0; nf < 7; nf++) {
                    uint32_t b[2];
                    ldsm2(b, kb + (uint32_t)(nf * 8 * 528) + ks * 32);
                    mma16816(sc[0][nf], a[0], b);
                    mma16816(sc[1][nf], a[1], b);
                }
            }
        }
        gbar(bid);   // group's Q/K reads done
        pre_b0(W4 + 2 * W_MAT_U4 + wfoff, nb);   // V B0 across softmax

        // ---- softmax (regs) + P store (overwrites own Q region) ----
        #pragma unroll
        for (int mf = 0; mf < 2; mf++)
            #pragma unroll
            for (int half = 0; half < 2; half++) {
                int lr = mfsA * 32 + mf * 16 + half * 8 + r0;
                float vv[14];
                float m = -1e30f;
                #pragma unroll
                for (int nf = 0; nf < 7; nf++)
                    #pragma unroll
                    for (int j = 0; j < 2; j++) {
                        int kk = nf * 8 + c0 + j;
                        float sv = (kk < NTOK) ? sc[mf][nf][half*2 + j] * 0.125f : -1e30f;
                        vv[nf*2 + j] = sv;
                        m = fmaxf(m, sv);
                    }
                m = fmaxf(m, __shfl_xor_sync(0xFFFFFFFFu, m, 1));
                m = fmaxf(m, __shfl_xor_sync(0xFFFFFFFFu, m, 2));
                float sum = 0.0f;
                #pragma unroll
                for (int t = 0; t < 14; t++) {
                    float e = (vv[t] > -1e29f) ? __expf(vv[t] - m) : 0.0f;
                    vv[t] = e; sum += e;
                }
                sum += __shfl_xor_sync(0xFFFFFFFFu, sum, 1);
                sum += __shfl_xor_sync(0xFFFFFFFFu, sum, 2);
                float inv = 1.0f / sum;
                char* prow = sm + qBase + hA * 9216 + lr * 144;
                #pragma unroll
                for (int nf = 0; nf < 7; nf++) {
                    uint32_t pk = (lr < NTOK) ? bfx2(vv[nf*2] * inv, vv[nf*2+1] * inv) : 0u;
                    *(uint32_t*)(prow + (nf * 8 + c0) * 2) = pk;
                }
                *(uint32_t*)(prow + (56 + c0) * 2) = 0u;
            }

        // ---- V GEMM; epilogue -> own VT + g_R (pad rows: bf16 zeros) ----
        mma_gemm(aG, W4 + 2 * W_MAT_U4 + wfoff, acc, nb);
        #pragma unroll
        for (int mf = 0; mf < 4; mf++)
            #pragma unroll
            for (int rr = 0; rr < 2; rr++) {
                int lr = mf * 16 + r0 + rr * 8;
                if (lr < NTOK) {
                    const float* xs = xb + lr * 256;
                    float2 xv[4];
                    #pragma unroll
                    for (int nf = 0; nf < 4; nf++)
                        xv[nf] = __ldg((const float2*)(xs + nq * 32 + nf * 8 + c0));
                    #pragma unroll
                    for (int nf = 0; nf < 4; nf++) {
                        int c = nq * 32 + nf * 8 + c0;
                        float v0 = (acc[mf][nf][rr*2]   + sBias[512+c])   * 0.1f + xv[nf].x * 0.95f;
                        float v1 = (acc[mf][nf][rr*2+1] + sBias[512+c+1]) * 0.1f + xv[nf].y * 0.95f;
                        *(float2*)(Rb + lr * 256 + c) = make_float2(v0, v1);
                        *(__nv_bfloat16*)(sm + kBase + c * 144 + lr * 2)       = __float2bfloat16(v0);
                        *(__nv_bfloat16*)(sm + kBase + (c + 1) * 144 + lr * 2) = __float2bfloat16(v1);
                    }
                } else {
                    const __nv_bfloat16 z = __float2bfloat16(0.0f);
                    #pragma unroll
                    for (int nf = 0; nf < 4; nf++) {
                        int c = nq * 32 + nf * 8 + c0;
                        *(__nv_bfloat16*)(sm + kBase + c * 144 + lr * 2)       = z;
                        *(__nv_bfloat16*)(sm + kBase + (c + 1) * 144 + lr * 2) = z;
                    }
                }
            }
        gbar(bid);   // own P + VT complete

        // ---- PV MMAs: warp (hA, mfsA): m32 rows x n64 head cols ----
        {
            float pa[2][8][4];
            #pragma unroll
            for (int mf = 0; mf < 2; mf++)
                #pragma unroll
                for (int nf = 0; nf < 8; nf++)
                    #pragma unroll
                    for (int q = 0; q < 4; q++) pa[mf][nf][q] = 0.0f;

            uint32_t pbase = sb + (uint32_t)(qBase + hA * 9216 + mfsA * 32 * 144) + aoffP;
            uint32_t vtb = sb + (uint32_t)kBase
                         + (uint32_t)((hA * 64 + (lane & 7)) * 144)
                         + (uint32_t)(((lane >> 3) & 1) * 16);
            #pragma unroll
            for (int ks = 0; ks < 4; ks++) {
                uint32_t a[2][4];
                ldsm4(a[0], pbase + ks * 32);
                ldsm4(a[1], pbase + 16 * 144 + ks * 32);
                #pragma unroll
                for (int nf = 0; nf < 8; nf++) {
                    uint32_t b[2];
                    ldsm2(b, vtb + (uint32_t)(nf * 8 * 144) + ks * 32);
                    mma16816(pa[0][nf], a[0], b);
                    mma16816(pa[1][nf], a[1], b);
                }
            }
            gbar(bid);   // group's P/VT reads done; own regions free for F32
            pre_b0(W4 + 3 * W_MAT_U4 + wfoff, nb);   // FFN1 B0 across PV epilogue

            // ---- PV epilogue: x2 = PV*0.1 + V'*0.95 -> own F32 + bf16 X ----
            #pragma unroll
            for (int mf = 0; mf < 2; mf++)
                #pragma unroll
                for (int rr = 0; rr < 2; rr++) {
                    int lr = mfsA * 32 + mf * 16 + rr * 8 + r0;
                    int rG = mh * 64 + lr;
                    if (lr < NTOK) {
                        float2 rv[8];
                        #pragma unroll
                        for (int nf = 0; nf < 8; nf++)
                            rv[nf] = *(const float2*)(Rb + lr * 256 + hA * 64 + nf * 8 + c0);
                        #pragma unroll
                        for (int nf = 0; nf < 8; nf++) {
                            int c = hA * 64 + nf * 8 + c0;
                            float a0 = pa[mf][nf][rr*2]   * 0.1f + rv[nf].x * 0.95f;
                            float a1 = pa[mf][nf][rr*2+1] * 0.1f + rv[nf].y * 0.95f;
                            *(float2*)(sm + F32ADDR(mh, lr, c)) = make_float2(a0, a1);
                            *(uint32_t*)(sm + SM_X + rG * 528 + c * 2) = bfx2(a0, a1);
                        }
                    }
                }
        }
        gbar(bid);

        // ---- FFN in (reads own bf16 x2 tile) ----
        mma_gemm(aG, W4 + 3 * W_MAT_U4 + wfoff, acc, nb);
        pre_b0(W4 + 4 * W_MAT_U4 + wfoff, nb);   // FFN2 B0 across FFN1 epilogue
        gbar(bid);           // group's x2 reads done
        #pragma unroll
        for (int mf = 0; mf < 4; mf++)
            #pragma unroll
            for (int rr = 0; rr < 2; rr++) {
                int lr = mf * 16 + r0 + rr * 8;
                int rG = mh * 64 + lr;
                if (lr < NTOK) {
                    float2 rv[4];
                    #pragma unroll
                    for (int nf = 0; nf < 4; nf++)
                        rv[nf] = *(const float2*)(sm + F32ADDR(mh, lr, nq * 32 + nf * 8 + c0));
                    #pragma unroll
                    for (int nf = 0; nf < 4; nf++) {
                        int c = nq * 32 + nf * 8 + c0;
                        float t2a = (acc[mf][nf][rr*2]   + sBias[768+c])   * 0.1f + rv[nf].x * 0.95f;
                        float t2b = (acc[mf][nf][rr*2+1] + sBias[768+c+1]) * 0.1f + rv[nf].y * 0.95f;
                        float t3a = (1.0f/(1.0f + __expf(-t2a)) - 0.5f) * 0.1f + t2a * 0.95f;
                        float t3b = (1.0f/(1.0f + __expf(-t2b)) - 0.5f) * 0.1f + t2b * 0.95f;
                        *(float2*)(sm + F32ADDR(mh, lr, c)) = make_float2(t3a, t3b);
                        *(uint32_t*)(sm + SM_X + rG * 528 + c * 2) = bfx2(t3a, t3b);
                    }
                }
            }
        gbar(bid);

        // ---- FFN out ----
        mma_gemm(aG, W4 + 4 * W_MAT_U4 + wfoff, acc, nb);
        #pragma unroll
        for (int mf = 0; mf < 4; mf++)
            #pragma unroll
            for (int rr = 0; rr < 2; rr++) {
                int lr = mf * 16 + r0 + rr * 8;
                if (lr < NTOK) {
                    float2 rv[4];
                    #pragma unroll
                    for (int nf = 0; nf < 4; nf++)
                        rv[nf] = *(const float2*)(sm + F32ADDR(mh, lr, nq * 32 + nf * 8 + c0));
                    #pragma unroll
                    for (int nf = 0; nf < 4; nf++) {
                        int c = nq * 32 + nf * 8 + c0;
                        float o0 = (acc[mf][nf][rr*2]   + sBias[1024+c])   * 0.1f + rv[nf].x * 0.95f;
                        float o1 = (acc[mf][nf][rr*2+1] + sBias[1024+c+1]) * 0.1f + rv[nf].y * 0.95f;
                        *(float2*)(ob + lr * 256 + c) = make_float2(o0, o1);
                    }
                }
            }
    }
}

// ---------------------------------------------------------------------------
extern "C" void kernel_launch(void* const* d_in, const int* in_sizes, int n_in,
                              void* d_out, int out_size)
{
    std_kernel<<<5 * DIM + 5, 256>>>(
        (const float*)d_in[1], (const float*)d_in[2],
        (const float*)d_in[3], (const float*)d_in[4],
        (const float*)d_in[5], (const float*)d_in[6],
        (const float*)d_in[7], (const float*)d_in[8],
        (const float*)d_in[9], (const float*)d_in[10]);

    cudaFuncSetAttribute(irmb_kernel,
                         cudaFuncAttributeMaxDynamicSharedMemorySize, SMEM_TOTAL);
    irmb_kernel<<<GRID, NT, SMEM_TOTAL>>>((const float*)d_in[0], (float*)d_out);
}